// round 2
// baseline (speedup 1.0000x reference)
#include <cuda_runtime.h>
#include <math.h>

#define BATCH   4096
#define NROWS   8192
#define DIM     512
#define TAU_INV 10.0f

#define TM 128
#define TN 128
#define TK 16
#define CSPLIT 16
#define TILES_PER_SPLIT ((NROWS / TN) / CSPLIT)   // 4

// Scratch (device globals: no runtime allocation)
__device__ float        d_Xn[(size_t)NROWS * DIM];   // normalized [A;B], 16 MB
__device__ float        d_gsum[NROWS];               // sum of exp(10c-10) over j != r
__device__ unsigned int d_gmax[NROWS];               // encoded row max of c (j != r)
__device__ float        d_gd[NROWS];                 // partner dot c = G[r, r^4096]
__device__ float        d_loss;
__device__ int          d_correct;

// Order-preserving float<->uint encoding for atomicMax on float
__device__ __forceinline__ unsigned int fenc(float f) {
    unsigned int u = __float_as_uint(f);
    return (u & 0x80000000u) ? ~u : (u | 0x80000000u);
}
__device__ __forceinline__ float fdec(unsigned int u) {
    u = (u & 0x80000000u) ? (u & 0x7FFFFFFFu) : ~u;
    return __uint_as_float(u);
}

// ---------------------------------------------------------------------------
__global__ void zero_kernel() {
    int i = blockIdx.x * blockDim.x + threadIdx.x;
    if (i < NROWS) {
        d_gsum[i] = 0.0f;
        d_gmax[i] = 0u;        // 0 < fenc(x) for all finite x
        d_gd[i]   = 0.0f;
    }
    if (i == 0) { d_loss = 0.0f; d_correct = 0; }
}

// ---------------------------------------------------------------------------
// One block per row of X. Row r<BATCH comes from view_a, else view_b.
__global__ void norm_kernel(const float* __restrict__ a,
                            const float* __restrict__ b) {
    int r = blockIdx.x;
    const float* src = (r < BATCH) ? a + (size_t)r * DIM
                                   : b + (size_t)(r - BATCH) * DIM;
    int t = threadIdx.x;   // 128 threads, 4 floats each
    float4 v = reinterpret_cast<const float4*>(src)[t];
    float ss = v.x * v.x + v.y * v.y + v.z * v.z + v.w * v.w;
    #pragma unroll
    for (int o = 16; o > 0; o >>= 1) ss += __shfl_xor_sync(0xffffffffu, ss, o);
    __shared__ float ws[4];
    if ((t & 31) == 0) ws[t >> 5] = ss;
    __syncthreads();
    float tot = ws[0] + ws[1] + ws[2] + ws[3];
    float scale = 1.0f / fmaxf(sqrtf(tot), 1e-12f);
    v.x *= scale; v.y *= scale; v.z *= scale; v.w *= scale;
    reinterpret_cast<float4*>(d_Xn + (size_t)r * DIM)[t] = v;
}

// ---------------------------------------------------------------------------
// Fused gram + softmax-stat kernel.
// Grid (NROWS/TM, CSPLIT), 256 threads. Block computes G tile rows
// [i0, i0+128) against TILES_PER_SPLIT column tiles of 128; epilogue
// accumulates per-row sum(exp(10c-10)) and max(c) with the self-diagonal
// excluded, and writes the partner dot (col == row ^ 4096) directly.
__global__ __launch_bounds__(256) void gram_kernel() {
    __shared__ float As[TK][TM + 4];
    __shared__ float Bs[TK][TN + 4];

    int tid = threadIdx.x;
    int tx = tid & 15;         // column group
    int ty = tid >> 4;         // row group
    int i0 = blockIdx.x * TM;

    float psum[8];
    float pmax[8];
    #pragma unroll
    for (int i = 0; i < 8; i++) { psum[i] = 0.0f; pmax[i] = -2.0f; }

    int lr = tid >> 2;               // 0..63 (row within half-tile)
    int lq = (tid & 3) * 4;          // k offset (float4 granule)

    for (int ct = 0; ct < TILES_PER_SPLIT; ct++) {
        int j0 = (blockIdx.y * TILES_PER_SPLIT + ct) * TN;

        float acc[8][8];
        #pragma unroll
        for (int i = 0; i < 8; i++)
            #pragma unroll
            for (int j = 0; j < 8; j++) acc[i][j] = 0.0f;

        for (int k0 = 0; k0 < DIM; k0 += TK) {
            float4 va0 = *reinterpret_cast<const float4*>(
                &d_Xn[(size_t)(i0 + lr)      * DIM + k0 + lq]);
            float4 va1 = *reinterpret_cast<const float4*>(
                &d_Xn[(size_t)(i0 + lr + 64) * DIM + k0 + lq]);
            float4 vb0 = *reinterpret_cast<const float4*>(
                &d_Xn[(size_t)(j0 + lr)      * DIM + k0 + lq]);
            float4 vb1 = *reinterpret_cast<const float4*>(
                &d_Xn[(size_t)(j0 + lr + 64) * DIM + k0 + lq]);

            __syncthreads();   // previous iteration's consumers done

            As[lq + 0][lr] = va0.x; As[lq + 1][lr] = va0.y;
            As[lq + 2][lr] = va0.z; As[lq + 3][lr] = va0.w;
            As[lq + 0][lr + 64] = va1.x; As[lq + 1][lr + 64] = va1.y;
            As[lq + 2][lr + 64] = va1.z; As[lq + 3][lr + 64] = va1.w;
            Bs[lq + 0][lr] = vb0.x; Bs[lq + 1][lr] = vb0.y;
            Bs[lq + 2][lr] = vb0.z; Bs[lq + 3][lr] = vb0.w;
            Bs[lq + 0][lr + 64] = vb1.x; Bs[lq + 1][lr + 64] = vb1.y;
            Bs[lq + 2][lr + 64] = vb1.z; Bs[lq + 3][lr + 64] = vb1.w;

            __syncthreads();

            #pragma unroll
            for (int kk = 0; kk < TK; kk++) {
                float af[8], bf[8];
                #pragma unroll
                for (int i = 0; i < 8; i++) af[i] = As[kk][ty * 8 + i];
                #pragma unroll
                for (int j = 0; j < 8; j++) bf[j] = Bs[kk][tx * 8 + j];
                #pragma unroll
                for (int i = 0; i < 8; i++)
                    #pragma unroll
                    for (int j = 0; j < 8; j++)
                        acc[i][j] = fmaf(af[i], bf[j], acc[i][j]);
            }
        }

        // Epilogue: fixed-max online softmax stats (logits in [-10,10])
        #pragma unroll
        for (int ri = 0; ri < 8; ri++) {
            int grow = i0 + ty * 8 + ri;
            int prt  = grow ^ BATCH;     // partner column
            #pragma unroll
            for (int cj = 0; cj < 8; cj++) {
                int gcol = j0 + tx * 8 + cj;
                float c = acc[ri][cj];
                if (gcol != grow) {
                    psum[ri] += __expf(fmaf(TAU_INV, c, -TAU_INV));
                    pmax[ri]  = fmaxf(pmax[ri], c);
                    if (gcol == prt) d_gd[grow] = c;   // exactly one writer globally
                }
            }
        }
    }

    // Cross-tx reduction in smem (reuse tile buffers, stride TM+1 = conflict-free)
    __syncthreads();
    float* rs = &As[0][0];   // 16*129 = 2064 <= 16*132
    float* rm = &Bs[0][0];
    #pragma unroll
    for (int ri = 0; ri < 8; ri++) {
        int lrow = ty * 8 + ri;
        rs[tx * (TM + 1) + lrow] = psum[ri];
        rm[tx * (TM + 1) + lrow] = pmax[ri];
    }
    __syncthreads();
    if (tid < TM) {
        float s = 0.0f, m = -2.0f;
        #pragma unroll
        for (int x = 0; x < 16; x++) {
            s += rs[x * (TM + 1) + tid];
            m  = fmaxf(m, rm[x * (TM + 1) + tid]);
        }
        int grow = i0 + tid;
        atomicAdd(&d_gsum[grow], s);
        atomicMax(&d_gmax[grow], fenc(m));
    }
}

// ---------------------------------------------------------------------------
__global__ void finalize_kernel() {
    int r = blockIdx.x * blockDim.x + threadIdx.x;
    float lossv = 0.0f;
    int corr = 0;
    if (r < NROWS) {
        float s = d_gsum[r];
        float d = d_gd[r];
        // lse = 10 + log(sum exp(10c - 10));  label logit = 10*d
        lossv = (TAU_INV + __logf(s)) - TAU_INV * d;
        if (r < BATCH) {
            float m = fdec(d_gmax[r]);
            corr = (d >= m) ? 1 : 0;   // partner is included in max scan
        }
    }
    #pragma unroll
    for (int o = 16; o > 0; o >>= 1) {
        lossv += __shfl_xor_sync(0xffffffffu, lossv, o);
        corr  += __shfl_xor_sync(0xffffffffu, corr, o);
    }
    __shared__ float sl[8];
    __shared__ int   sc[8];
    int w = threadIdx.x >> 5, lane = threadIdx.x & 31;
    if (lane == 0) { sl[w] = lossv; sc[w] = corr; }
    __syncthreads();
    if (threadIdx.x == 0) {
        float L = 0.0f; int C = 0;
        #pragma unroll
        for (int i = 0; i < 8; i++) { L += sl[i]; C += sc[i]; }
        atomicAdd(&d_loss, L);
        atomicAdd(&d_correct, C);
    }
}

// ---------------------------------------------------------------------------
__global__ void writeout_kernel(float* out, int out_size) {
    if (threadIdx.x == 0) {
        out[0] = d_loss / (float)NROWS;
        if (out_size > 1)
            out[1] = 100.0f * (float)d_correct / (float)BATCH;
    }
}

// ---------------------------------------------------------------------------
extern "C" void kernel_launch(void* const* d_in, const int* in_sizes, int n_in,
                              void* d_out, int out_size) {
    const float* a = (const float*)d_in[0];
    const float* b = (const float*)d_in[1];
    float* out = (float*)d_out;

    zero_kernel<<<(NROWS + 255) / 256, 256>>>();
    norm_kernel<<<NROWS, 128>>>(a, b);
    dim3 grid(NROWS / TM, CSPLIT);
    gram_kernel<<<grid, 256>>>();
    finalize_kernel<<<NROWS / 256, 256>>>();
    writeout_kernel<<<1, 32>>>(out, out_size);
}

// round 4
// speedup vs baseline: 2.5730x; 2.5730x over previous
#include <cuda_runtime.h>
#include <cuda_bf16.h>
#include <math.h>
#include <stdint.h>

#define BATCH   4096
#define NROWS   8192
#define DIM     512
#define TAU_INV 10.0f

// Gram tiling
#define TM 128
#define TN 128
#define KC 32                 // k-chunk (2 k16 slices)
#define NCHUNKS (DIM / KC)    // 16

// SMEM layout: padded rows (16 bf16 data + 8 bf16 pad = 48B) for conflict-free ldmatrix
#define ROWB   48
#define SLICEB (128 * ROWB)           // 6144
#define MATB   (2 * SLICEB)           // 12288 (2 k16 slices)
#define OFF_AHI 0
#define OFF_ALO MATB
#define OFF_BHI (2 * MATB)
#define OFF_BLO (3 * MATB)
#define STAGEB  (4 * MATB)            // 49152
#define SMEM_TOTAL (2 * STAGEB)       // 98304

// ---------------------------------------------------------------------------
// Scratch (device globals: no runtime allocation)
__device__ __nv_bfloat16 d_Xhi[(size_t)NROWS * DIM];  // 8 MB
__device__ __nv_bfloat16 d_Xlo[(size_t)NROWS * DIM];  // 8 MB
__device__ float         d_gsum[NROWS];
__device__ unsigned int  d_gmax[NROWS];
__device__ float         d_gd[NROWS];
__device__ float         d_loss;
__device__ int           d_correct;

// ---------------------------------------------------------------------------
__device__ __forceinline__ uint32_t smem_to_u32(const void* p) {
    uint32_t a;
    asm("{ .reg .u64 t; cvta.to.shared.u64 t, %1; cvt.u32.u64 %0, t; }"
        : "=r"(a) : "l"(p));
    return a;
}

__device__ __forceinline__ void cp_async16(uint32_t dst, const void* src) {
    asm volatile("cp.async.cg.shared.global [%0], [%1], 16;"
                 :: "r"(dst), "l"(src) : "memory");
}
__device__ __forceinline__ void cp_commit() {
    asm volatile("cp.async.commit_group;" ::: "memory");
}
template <int N>
__device__ __forceinline__ void cp_wait() {
    asm volatile("cp.async.wait_group %0;" :: "n"(N) : "memory");
}

__device__ __forceinline__ void ldsm4(uint32_t* r, uint32_t addr) {
    asm volatile("ldmatrix.sync.aligned.m8n8.x4.shared.b16 {%0,%1,%2,%3}, [%4];"
                 : "=r"(r[0]), "=r"(r[1]), "=r"(r[2]), "=r"(r[3]) : "r"(addr));
}

__device__ __forceinline__ void mma16816(float* d, const uint32_t* a,
                                         uint32_t b0, uint32_t b1) {
    asm volatile(
        "mma.sync.aligned.m16n8k16.row.col.f32.bf16.bf16.f32 "
        "{%0,%1,%2,%3}, {%4,%5,%6,%7}, {%8,%9}, {%0,%1,%2,%3};\n"
        : "+f"(d[0]), "+f"(d[1]), "+f"(d[2]), "+f"(d[3])
        : "r"(a[0]), "r"(a[1]), "r"(a[2]), "r"(a[3]), "r"(b0), "r"(b1));
}

// Order-preserving float<->uint encoding for atomicMax on float
__device__ __forceinline__ unsigned int fenc(float f) {
    unsigned int u = __float_as_uint(f);
    return (u & 0x80000000u) ? ~u : (u | 0x80000000u);
}
__device__ __forceinline__ float fdec(unsigned int u) {
    u = (u & 0x80000000u) ? (u & 0x7FFFFFFFu) : ~u;
    return __uint_as_float(u);
}

// ---------------------------------------------------------------------------
__global__ void zero_kernel() {
    int i = blockIdx.x * blockDim.x + threadIdx.x;
    if (i < NROWS) {
        d_gsum[i] = 0.0f;
        d_gmax[i] = 0u;
        d_gd[i]   = 0.0f;
    }
    if (i == 0) { d_loss = 0.0f; d_correct = 0; }
}

// ---------------------------------------------------------------------------
// Normalize rows and split into bf16 (hi, lo): x = hi + lo (+ O(2^-18)).
__global__ void norm_kernel(const float* __restrict__ a,
                            const float* __restrict__ b) {
    int r = blockIdx.x;
    const float* src = (r < BATCH) ? a + (size_t)r * DIM
                                   : b + (size_t)(r - BATCH) * DIM;
    int t = threadIdx.x;   // 128 threads, 4 floats each
    float4 v = reinterpret_cast<const float4*>(src)[t];
    float ss = v.x * v.x + v.y * v.y + v.z * v.z + v.w * v.w;
    #pragma unroll
    for (int o = 16; o > 0; o >>= 1) ss += __shfl_xor_sync(0xffffffffu, ss, o);
    __shared__ float ws[4];
    if ((t & 31) == 0) ws[t >> 5] = ss;
    __syncthreads();
    float tot = ws[0] + ws[1] + ws[2] + ws[3];
    float scale = 1.0f / fmaxf(sqrtf(tot), 1e-12f);
    v.x *= scale; v.y *= scale; v.z *= scale; v.w *= scale;

    __nv_bfloat16 hx = __float2bfloat16(v.x);
    __nv_bfloat16 hy = __float2bfloat16(v.y);
    __nv_bfloat16 hz = __float2bfloat16(v.z);
    __nv_bfloat16 hw = __float2bfloat16(v.w);
    float lx = v.x - __bfloat162float(hx);
    float ly = v.y - __bfloat162float(hy);
    float lz = v.z - __bfloat162float(hz);
    float lw = v.w - __bfloat162float(hw);

    __nv_bfloat162* dh = reinterpret_cast<__nv_bfloat162*>(d_Xhi + (size_t)r * DIM);
    __nv_bfloat162* dl = reinterpret_cast<__nv_bfloat162*>(d_Xlo + (size_t)r * DIM);
    dh[2 * t]     = __nv_bfloat162(hx, hy);
    dh[2 * t + 1] = __nv_bfloat162(hz, hw);
    dl[2 * t]     = __floats2bfloat162_rn(lx, ly);
    dl[2 * t + 1] = __floats2bfloat162_rn(lz, lw);
}

// ---------------------------------------------------------------------------
// Gram kernel: CTA = 128x128 tile of G = X.X^T via mma.sync bf16 (3 chains:
// hi.hi + hi.lo + lo.hi, fp32 accum). cp.async double-buffered K chunks.
// Epilogue: per-row sum(exp(10c-10)) and max(c), self-diagonal excluded,
// partner dot written directly.
__global__ __launch_bounds__(256, 2) void gram_kernel() {
    extern __shared__ __align__(1024) unsigned char smem[];
    uint32_t sbase = smem_to_u32(smem);

    const int tid  = threadIdx.x;
    const int lane = tid & 31;
    const int wid  = tid >> 5;
    const int wy   = wid & 3;    // M warp (4)
    const int wx   = wid >> 2;   // N warp (2)

    const int i0 = blockIdx.y * TM;
    const int j0 = blockIdx.x * TN;

    float c[2][8][4];
    #pragma unroll
    for (int mt = 0; mt < 2; mt++)
        #pragma unroll
        for (int nt = 0; nt < 8; nt++)
            #pragma unroll
            for (int q = 0; q < 4; q++) c[mt][nt][q] = 0.0f;

    // cp.async loader: one stage = 2048 16B chunks, 8 per thread.
    // idx bits: h=bit0, r=bits1..7, s=bit8, m=bits9..10
    auto load_stage = [&](int st, int k0) {
        #pragma unroll
        for (int it = 0; it < 8; it++) {
            int idx = tid + it * 256;
            int h = idx & 1;
            int r = (idx >> 1) & 127;
            int s = (idx >> 8) & 1;
            int m = idx >> 9;                     // 0=Ahi 1=Bhi 2=Alo 3=Blo
            int rowbase = (m & 1) ? j0 : i0;
            const __nv_bfloat16* g =
                ((m < 2) ? d_Xhi : d_Xlo) +
                (size_t)(rowbase + r) * DIM + k0 + s * 16 + h * 8;
            uint32_t dst = sbase + st * STAGEB +
                           ((m & 1) ? OFF_BHI : 0) + ((m >> 1) ? OFF_ALO : 0) +
                           s * SLICEB + r * ROWB + h * 16;
            cp_async16(dst, g);
        }
        cp_commit();
    };

    // ldmatrix lane offset: row = (lane&7) + ((lane>>3)&1)*8, khalf = lane>>4
    const uint32_t laneoff =
        (uint32_t)(((lane & 7) + ((lane >> 3) & 1) * 8) * ROWB + (lane >> 4) * 16);

    load_stage(0, 0);
    int stage = 0;

    for (int ch = 0; ch < NCHUNKS; ch++) {
        if (ch + 1 < NCHUNKS) load_stage(stage ^ 1, (ch + 1) * KC);
        if (ch + 1 < NCHUNKS) cp_wait<1>(); else cp_wait<0>();
        __syncthreads();

        uint32_t sb = sbase + stage * STAGEB;
        #pragma unroll
        for (int s = 0; s < 2; s++) {
            uint32_t slice = sb + s * SLICEB;
            uint32_t ahi[2][4], alo[2][4], bb[4][4];
            #pragma unroll
            for (int mt = 0; mt < 2; mt++) {
                uint32_t arow = (uint32_t)((wy * 32 + mt * 16) * ROWB) + laneoff;
                ldsm4(ahi[mt], slice + OFF_AHI + arow);
                ldsm4(alo[mt], slice + OFF_ALO + arow);
            }
            // Bhi: hi.hi and lo.hi
            #pragma unroll
            for (int bt = 0; bt < 4; bt++) {
                uint32_t brow = (uint32_t)((wx * 64 + bt * 16) * ROWB) + laneoff;
                ldsm4(bb[bt], slice + OFF_BHI + brow);
            }
            #pragma unroll
            for (int mt = 0; mt < 2; mt++)
                #pragma unroll
                for (int bt = 0; bt < 4; bt++) {
                    mma16816(c[mt][bt * 2 + 0], ahi[mt], bb[bt][0], bb[bt][2]);
                    mma16816(c[mt][bt * 2 + 1], ahi[mt], bb[bt][1], bb[bt][3]);
                    mma16816(c[mt][bt * 2 + 0], alo[mt], bb[bt][0], bb[bt][2]);
                    mma16816(c[mt][bt * 2 + 1], alo[mt], bb[bt][1], bb[bt][3]);
                }
            // Blo: hi.lo
            #pragma unroll
            for (int bt = 0; bt < 4; bt++) {
                uint32_t brow = (uint32_t)((wx * 64 + bt * 16) * ROWB) + laneoff;
                ldsm4(bb[bt], slice + OFF_BLO + brow);
            }
            #pragma unroll
            for (int mt = 0; mt < 2; mt++)
                #pragma unroll
                for (int bt = 0; bt < 4; bt++) {
                    mma16816(c[mt][bt * 2 + 0], ahi[mt], bb[bt][0], bb[bt][2]);
                    mma16816(c[mt][bt * 2 + 1], ahi[mt], bb[bt][1], bb[bt][3]);
                }
        }
        __syncthreads();
        stage ^= 1;
    }

    // Epilogue: fixed-max softmax stats (logits = 10c in [-10,10])
    #pragma unroll
    for (int mt = 0; mt < 2; mt++) {
        int r0 = i0 + wy * 32 + mt * 16 + (lane >> 2);
        int r1 = r0 + 8;
        float s0 = 0.0f, s1 = 0.0f, m0 = -2.0f, m1 = -2.0f;
        #pragma unroll
        for (int nt = 0; nt < 8; nt++) {
            int c0 = j0 + wx * 64 + nt * 8 + (lane & 3) * 2;
            #pragma unroll
            for (int q = 0; q < 4; q++) {
                float v  = c[mt][nt][q];
                int gr   = (q & 2) ? r1 : r0;
                int gc   = c0 + (q & 1);
                if (gc != gr) {
                    float e = __expf(fmaf(TAU_INV, v, -TAU_INV));
                    if (q & 2) { s1 += e; m1 = fmaxf(m1, v); }
                    else       { s0 += e; m0 = fmaxf(m0, v); }
                    if (gc == (gr ^ BATCH)) d_gd[gr] = v;   // one writer globally
                }
            }
        }
        #pragma unroll
        for (int o = 1; o < 4; o <<= 1) {
            s0 += __shfl_xor_sync(0xffffffffu, s0, o);
            s1 += __shfl_xor_sync(0xffffffffu, s1, o);
            m0 = fmaxf(m0, __shfl_xor_sync(0xffffffffu, m0, o));
            m1 = fmaxf(m1, __shfl_xor_sync(0xffffffffu, m1, o));
        }
        if ((lane & 3) == 0) {
            atomicAdd(&d_gsum[r0], s0);
            atomicAdd(&d_gsum[r1], s1);
            if (r0 < BATCH) atomicMax(&d_gmax[r0], fenc(m0));
            if (r1 < BATCH) atomicMax(&d_gmax[r1], fenc(m1));
        }
    }
}

// ---------------------------------------------------------------------------
__global__ void finalize_kernel() {
    int r = blockIdx.x * blockDim.x + threadIdx.x;
    float lossv = 0.0f;
    int corr = 0;
    if (r < NROWS) {
        float s = d_gsum[r];
        float d = d_gd[r];
        // lse = 10 + log(sum exp(10c - 10));  label logit = 10*d
        lossv = (TAU_INV + __logf(s)) - TAU_INV * d;
        if (r < BATCH) {
            float m = fdec(d_gmax[r]);
            corr = (d >= m) ? 1 : 0;   // partner included in the max scan
        }
    }
    #pragma unroll
    for (int o = 16; o > 0; o >>= 1) {
        lossv += __shfl_xor_sync(0xffffffffu, lossv, o);
        corr  += __shfl_xor_sync(0xffffffffu, corr, o);
    }
    __shared__ float sl[8];
    __shared__ int   sc[8];
    int w = threadIdx.x >> 5, lane = threadIdx.x & 31;
    if (lane == 0) { sl[w] = lossv; sc[w] = corr; }
    __syncthreads();
    if (threadIdx.x == 0) {
        float L = 0.0f; int C = 0;
        #pragma unroll
        for (int i = 0; i < 8; i++) { L += sl[i]; C += sc[i]; }
        atomicAdd(&d_loss, L);
        atomicAdd(&d_correct, C);
    }
}

// ---------------------------------------------------------------------------
__global__ void writeout_kernel(float* out, int out_size) {
    if (threadIdx.x == 0) {
        out[0] = d_loss / (float)NROWS;
        if (out_size > 1)
            out[1] = 100.0f * (float)d_correct / (float)BATCH;
    }
}

// ---------------------------------------------------------------------------
extern "C" void kernel_launch(void* const* d_in, const int* in_sizes, int n_in,
                              void* d_out, int out_size) {
    const float* a = (const float*)d_in[0];
    const float* b = (const float*)d_in[1];
    float* out = (float*)d_out;

    cudaFuncSetAttribute(gram_kernel,
                         cudaFuncAttributeMaxDynamicSharedMemorySize, SMEM_TOTAL);

    zero_kernel<<<(NROWS + 255) / 256, 256>>>();
    norm_kernel<<<NROWS, 128>>>(a, b);
    dim3 grid(NROWS / TN, NROWS / TM);
    gram_kernel<<<grid, 256, SMEM_TOTAL>>>();
    finalize_kernel<<<NROWS / 256, 256>>>();
    writeout_kernel<<<1, 32>>>(out, out_size);
}

// round 5
// speedup vs baseline: 2.5735x; 1.0002x over previous
#include <cuda_runtime.h>
#include <cuda_bf16.h>
#include <math.h>
#include <stdint.h>

#define BATCH   4096
#define NROWS   8192
#define DIM     512
#define TAU_INV 10.0f

// Gram tiling
#define TM 128
#define TN 128
#define KC 32                 // k-chunk (2 k16 slices)
#define NCHUNKS (DIM / KC)    // 16

// SMEM layout: padded rows (16 bf16 data + 8 bf16 pad = 48B) for conflict-free ldmatrix
#define ROWB   48
#define SLICEB (128 * ROWB)           // 6144
#define MATB   (2 * SLICEB)           // 12288 (2 k16 slices)
#define OFF_AHI 0
#define OFF_ALO MATB
#define OFF_BHI (2 * MATB)
#define OFF_BLO (3 * MATB)
#define STAGEB  (4 * MATB)            // 49152
#define SMEM_TOTAL (2 * STAGEB)       // 98304

// ---------------------------------------------------------------------------
// Scratch (device globals: no runtime allocation)
__device__ __nv_bfloat16 d_Xhi[(size_t)NROWS * DIM];  // 8 MB
__device__ __nv_bfloat16 d_Xlo[(size_t)NROWS * DIM];  // 8 MB
__device__ float         d_gsum[NROWS];
__device__ unsigned int  d_gmax[NROWS];
__device__ float         d_gd[NROWS];
__device__ float         d_loss;
__device__ int           d_correct;

// ---------------------------------------------------------------------------
__device__ __forceinline__ uint32_t smem_to_u32(const void* p) {
    uint32_t a;
    asm("{ .reg .u64 t; cvta.to.shared.u64 t, %1; cvt.u32.u64 %0, t; }"
        : "=r"(a) : "l"(p));
    return a;
}

__device__ __forceinline__ void cp_async16(uint32_t dst, const void* src) {
    asm volatile("cp.async.cg.shared.global [%0], [%1], 16;"
                 :: "r"(dst), "l"(src) : "memory");
}
__device__ __forceinline__ void cp_commit() {
    asm volatile("cp.async.commit_group;" ::: "memory");
}
template <int N>
__device__ __forceinline__ void cp_wait() {
    asm volatile("cp.async.wait_group %0;" :: "n"(N) : "memory");
}

__device__ __forceinline__ void ldsm4(uint32_t* r, uint32_t addr) {
    asm volatile("ldmatrix.sync.aligned.m8n8.x4.shared.b16 {%0,%1,%2,%3}, [%4];"
                 : "=r"(r[0]), "=r"(r[1]), "=r"(r[2]), "=r"(r[3]) : "r"(addr));
}

__device__ __forceinline__ void mma16816(float* d, const uint32_t* a,
                                         uint32_t b0, uint32_t b1) {
    asm volatile(
        "mma.sync.aligned.m16n8k16.row.col.f32.bf16.bf16.f32 "
        "{%0,%1,%2,%3}, {%4,%5,%6,%7}, {%8,%9}, {%0,%1,%2,%3};\n"
        : "+f"(d[0]), "+f"(d[1]), "+f"(d[2]), "+f"(d[3])
        : "r"(a[0]), "r"(a[1]), "r"(a[2]), "r"(a[3]), "r"(b0), "r"(b1));
}

// Order-preserving float<->uint encoding for atomicMax on float
__device__ __forceinline__ unsigned int fenc(float f) {
    unsigned int u = __float_as_uint(f);
    return (u & 0x80000000u) ? ~u : (u | 0x80000000u);
}
__device__ __forceinline__ float fdec(unsigned int u) {
    u = (u & 0x80000000u) ? (u & 0x7FFFFFFFu) : ~u;
    return __uint_as_float(u);
}

// ---------------------------------------------------------------------------
__global__ void zero_kernel() {
    int i = blockIdx.x * blockDim.x + threadIdx.x;
    if (i < NROWS) {
        d_gsum[i] = 0.0f;
        d_gmax[i] = 0u;
        d_gd[i]   = 0.0f;
    }
    if (i == 0) { d_loss = 0.0f; d_correct = 0; }
}

// ---------------------------------------------------------------------------
// Normalize rows and split into bf16 (hi, lo): x = hi + lo (+ O(2^-18)).
__global__ void norm_kernel(const float* __restrict__ a,
                            const float* __restrict__ b) {
    int r = blockIdx.x;
    const float* src = (r < BATCH) ? a + (size_t)r * DIM
                                   : b + (size_t)(r - BATCH) * DIM;
    int t = threadIdx.x;   // 128 threads, 4 floats each
    float4 v = reinterpret_cast<const float4*>(src)[t];
    float ss = v.x * v.x + v.y * v.y + v.z * v.z + v.w * v.w;
    #pragma unroll
    for (int o = 16; o > 0; o >>= 1) ss += __shfl_xor_sync(0xffffffffu, ss, o);
    __shared__ float ws[4];
    if ((t & 31) == 0) ws[t >> 5] = ss;
    __syncthreads();
    float tot = ws[0] + ws[1] + ws[2] + ws[3];
    float scale = 1.0f / fmaxf(sqrtf(tot), 1e-12f);
    v.x *= scale; v.y *= scale; v.z *= scale; v.w *= scale;

    __nv_bfloat16 hx = __float2bfloat16(v.x);
    __nv_bfloat16 hy = __float2bfloat16(v.y);
    __nv_bfloat16 hz = __float2bfloat16(v.z);
    __nv_bfloat16 hw = __float2bfloat16(v.w);
    float lx = v.x - __bfloat162float(hx);
    float ly = v.y - __bfloat162float(hy);
    float lz = v.z - __bfloat162float(hz);
    float lw = v.w - __bfloat162float(hw);

    __nv_bfloat162* dh = reinterpret_cast<__nv_bfloat162*>(d_Xhi + (size_t)r * DIM);
    __nv_bfloat162* dl = reinterpret_cast<__nv_bfloat162*>(d_Xlo + (size_t)r * DIM);
    dh[2 * t]     = __nv_bfloat162(hx, hy);
    dh[2 * t + 1] = __nv_bfloat162(hz, hw);
    dl[2 * t]     = __floats2bfloat162_rn(lx, ly);
    dl[2 * t + 1] = __floats2bfloat162_rn(lz, lw);
}

// ---------------------------------------------------------------------------
// Gram kernel: CTA = 128x128 tile of G = X.X^T via mma.sync bf16 (3 chains:
// hi.hi + hi.lo + lo.hi, fp32 accum). cp.async double-buffered K chunks.
// Epilogue: per-row sum(exp(10c-10)) and max(c), self-diagonal excluded,
// partner dot written directly.
__global__ __launch_bounds__(256, 2) void gram_kernel() {
    extern __shared__ __align__(1024) unsigned char smem[];
    uint32_t sbase = smem_to_u32(smem);

    const int tid  = threadIdx.x;
    const int lane = tid & 31;
    const int wid  = tid >> 5;
    const int wy   = wid & 3;    // M warp (4)
    const int wx   = wid >> 2;   // N warp (2)

    const int i0 = blockIdx.y * TM;
    const int j0 = blockIdx.x * TN;

    float c[2][8][4];
    #pragma unroll
    for (int mt = 0; mt < 2; mt++)
        #pragma unroll
        for (int nt = 0; nt < 8; nt++)
            #pragma unroll
            for (int q = 0; q < 4; q++) c[mt][nt][q] = 0.0f;

    // cp.async loader: one stage = 2048 16B chunks, 8 per thread.
    // idx bits: h=bit0, r=bits1..7, s=bit8, m=bits9..10
    auto load_stage = [&](int st, int k0) {
        #pragma unroll
        for (int it = 0; it < 8; it++) {
            int idx = tid + it * 256;
            int h = idx & 1;
            int r = (idx >> 1) & 127;
            int s = (idx >> 8) & 1;
            int m = idx >> 9;                     // 0=Ahi 1=Bhi 2=Alo 3=Blo
            int rowbase = (m & 1) ? j0 : i0;
            const __nv_bfloat16* g =
                ((m < 2) ? d_Xhi : d_Xlo) +
                (size_t)(rowbase + r) * DIM + k0 + s * 16 + h * 8;
            uint32_t dst = sbase + st * STAGEB +
                           ((m & 1) ? OFF_BHI : 0) + ((m >> 1) ? OFF_ALO : 0) +
                           s * SLICEB + r * ROWB + h * 16;
            cp_async16(dst, g);
        }
        cp_commit();
    };

    // ldmatrix lane offset: row = (lane&7) + ((lane>>3)&1)*8, khalf = lane>>4
    const uint32_t laneoff =
        (uint32_t)(((lane & 7) + ((lane >> 3) & 1) * 8) * ROWB + (lane >> 4) * 16);

    load_stage(0, 0);
    int stage = 0;

    for (int ch = 0; ch < NCHUNKS; ch++) {
        if (ch + 1 < NCHUNKS) load_stage(stage ^ 1, (ch + 1) * KC);
        if (ch + 1 < NCHUNKS) cp_wait<1>(); else cp_wait<0>();
        __syncthreads();

        uint32_t sb = sbase + stage * STAGEB;
        #pragma unroll
        for (int s = 0; s < 2; s++) {
            uint32_t slice = sb + s * SLICEB;
            uint32_t ahi[2][4], alo[2][4], bb[4][4];
            #pragma unroll
            for (int mt = 0; mt < 2; mt++) {
                uint32_t arow = (uint32_t)((wy * 32 + mt * 16) * ROWB) + laneoff;
                ldsm4(ahi[mt], slice + OFF_AHI + arow);
                ldsm4(alo[mt], slice + OFF_ALO + arow);
            }
            // Bhi: hi.hi and lo.hi
            #pragma unroll
            for (int bt = 0; bt < 4; bt++) {
                uint32_t brow = (uint32_t)((wx * 64 + bt * 16) * ROWB) + laneoff;
                ldsm4(bb[bt], slice + OFF_BHI + brow);
            }
            #pragma unroll
            for (int mt = 0; mt < 2; mt++)
                #pragma unroll
                for (int bt = 0; bt < 4; bt++) {
                    mma16816(c[mt][bt * 2 + 0], ahi[mt], bb[bt][0], bb[bt][2]);
                    mma16816(c[mt][bt * 2 + 1], ahi[mt], bb[bt][1], bb[bt][3]);
                    mma16816(c[mt][bt * 2 + 0], alo[mt], bb[bt][0], bb[bt][2]);
                    mma16816(c[mt][bt * 2 + 1], alo[mt], bb[bt][1], bb[bt][3]);
                }
            // Blo: hi.lo
            #pragma unroll
            for (int bt = 0; bt < 4; bt++) {
                uint32_t brow = (uint32_t)((wx * 64 + bt * 16) * ROWB) + laneoff;
                ldsm4(bb[bt], slice + OFF_BLO + brow);
            }
            #pragma unroll
            for (int mt = 0; mt < 2; mt++)
                #pragma unroll
                for (int bt = 0; bt < 4; bt++) {
                    mma16816(c[mt][bt * 2 + 0], ahi[mt], bb[bt][0], bb[bt][2]);
                    mma16816(c[mt][bt * 2 + 1], ahi[mt], bb[bt][1], bb[bt][3]);
                }
        }
        __syncthreads();
        stage ^= 1;
    }

    // Epilogue: fixed-max softmax stats (logits = 10c in [-10,10])
    #pragma unroll
    for (int mt = 0; mt < 2; mt++) {
        int r0 = i0 + wy * 32 + mt * 16 + (lane >> 2);
        int r1 = r0 + 8;
        float s0 = 0.0f, s1 = 0.0f, m0 = -2.0f, m1 = -2.0f;
        #pragma unroll
        for (int nt = 0; nt < 8; nt++) {
            int c0 = j0 + wx * 64 + nt * 8 + (lane & 3) * 2;
            #pragma unroll
            for (int q = 0; q < 4; q++) {
                float v  = c[mt][nt][q];
                int gr   = (q & 2) ? r1 : r0;
                int gc   = c0 + (q & 1);
                if (gc != gr) {
                    float e = __expf(fmaf(TAU_INV, v, -TAU_INV));
                    if (q & 2) { s1 += e; m1 = fmaxf(m1, v); }
                    else       { s0 += e; m0 = fmaxf(m0, v); }
                    if (gc == (gr ^ BATCH)) d_gd[gr] = v;   // one writer globally
                }
            }
        }
        #pragma unroll
        for (int o = 1; o < 4; o <<= 1) {
            s0 += __shfl_xor_sync(0xffffffffu, s0, o);
            s1 += __shfl_xor_sync(0xffffffffu, s1, o);
            m0 = fmaxf(m0, __shfl_xor_sync(0xffffffffu, m0, o));
            m1 = fmaxf(m1, __shfl_xor_sync(0xffffffffu, m1, o));
        }
        if ((lane & 3) == 0) {
            atomicAdd(&d_gsum[r0], s0);
            atomicAdd(&d_gsum[r1], s1);
            if (r0 < BATCH) atomicMax(&d_gmax[r0], fenc(m0));
            if (r1 < BATCH) atomicMax(&d_gmax[r1], fenc(m1));
        }
    }
}

// ---------------------------------------------------------------------------
__global__ void finalize_kernel() {
    int r = blockIdx.x * blockDim.x + threadIdx.x;
    float lossv = 0.0f;
    int corr = 0;
    if (r < NROWS) {
        float s = d_gsum[r];
        float d = d_gd[r];
        // lse = 10 + log(sum exp(10c - 10));  label logit = 10*d
        lossv = (TAU_INV + __logf(s)) - TAU_INV * d;
        if (r < BATCH) {
            float m = fdec(d_gmax[r]);
            corr = (d >= m) ? 1 : 0;   // partner included in the max scan
        }
    }
    #pragma unroll
    for (int o = 16; o > 0; o >>= 1) {
        lossv += __shfl_xor_sync(0xffffffffu, lossv, o);
        corr  += __shfl_xor_sync(0xffffffffu, corr, o);
    }
    __shared__ float sl[8];
    __shared__ int   sc[8];
    int w = threadIdx.x >> 5, lane = threadIdx.x & 31;
    if (lane == 0) { sl[w] = lossv; sc[w] = corr; }
    __syncthreads();
    if (threadIdx.x == 0) {
        float L = 0.0f; int C = 0;
        #pragma unroll
        for (int i = 0; i < 8; i++) { L += sl[i]; C += sc[i]; }
        atomicAdd(&d_loss, L);
        atomicAdd(&d_correct, C);
    }
}

// ---------------------------------------------------------------------------
__global__ void writeout_kernel(float* out, int out_size) {
    if (threadIdx.x == 0) {
        out[0] = d_loss / (float)NROWS;
        if (out_size > 1)
            out[1] = 100.0f * (float)d_correct / (float)BATCH;
    }
}

// ---------------------------------------------------------------------------
extern "C" void kernel_launch(void* const* d_in, const int* in_sizes, int n_in,
                              void* d_out, int out_size) {
    const float* a = (const float*)d_in[0];
    const float* b = (const float*)d_in[1];
    float* out = (float*)d_out;

    cudaFuncSetAttribute(gram_kernel,
                         cudaFuncAttributeMaxDynamicSharedMemorySize, SMEM_TOTAL);

    zero_kernel<<<(NROWS + 255) / 256, 256>>>();
    norm_kernel<<<NROWS, 128>>>(a, b);
    dim3 grid(NROWS / TN, NROWS / TM);
    gram_kernel<<<grid, 256, SMEM_TOTAL>>>();
    finalize_kernel<<<NROWS / 256, 256>>>();
    writeout_kernel<<<1, 32>>>(out, out_size);
}

// round 6
// speedup vs baseline: 4.6781x; 1.8178x over previous
#include <cuda_runtime.h>
#include <cuda_bf16.h>
#include <math.h>
#include <stdint.h>

#define BATCH   4096
#define NROWS   8192
#define DIM     512
#define TAU_INV 10.0f

// Gram tiling
#define TM 128
#define TN 128
#define KC 32                 // k-chunk (2 k16 slices)
#define NCHUNKS (DIM / KC)    // 16
#define NTILE   (NROWS / TN)  // 64
#define NBLOCKS (NTILE * (NTILE + 1) / 2)   // 2080 upper-triangle tiles

// SMEM layout: padded rows (16 bf16 data + 8 bf16 pad = 48B) for conflict-free ldmatrix
#define ROWB   48
#define SLICEB (128 * ROWB)           // 6144
#define MATB   (2 * SLICEB)           // 12288 (2 k16 slices)
#define OFF_AHI 0
#define OFF_ALO MATB
#define OFF_BHI (2 * MATB)
#define OFF_BLO (3 * MATB)
#define STAGEB  (4 * MATB)            // 49152
#define SMEM_TOTAL (2 * STAGEB)       // 98304

// ---------------------------------------------------------------------------
// Scratch (device globals: no runtime allocation)
__device__ __nv_bfloat16 d_Xhi[(size_t)NROWS * DIM];  // 8 MB
__device__ __nv_bfloat16 d_Xlo[(size_t)NROWS * DIM];  // 8 MB
__device__ float         d_gsum[NROWS];
__device__ unsigned int  d_gmax[NROWS];
__device__ float         d_gd[NROWS];
__device__ float         d_loss;
__device__ int           d_correct;

// ---------------------------------------------------------------------------
__device__ __forceinline__ uint32_t smem_to_u32(const void* p) {
    uint32_t a;
    asm("{ .reg .u64 t; cvta.to.shared.u64 t, %1; cvt.u32.u64 %0, t; }"
        : "=r"(a) : "l"(p));
    return a;
}

__device__ __forceinline__ void cp_async16(uint32_t dst, const void* src) {
    asm volatile("cp.async.cg.shared.global [%0], [%1], 16;"
                 :: "r"(dst), "l"(src) : "memory");
}
__device__ __forceinline__ void cp_commit() {
    asm volatile("cp.async.commit_group;" ::: "memory");
}
template <int N>
__device__ __forceinline__ void cp_wait() {
    asm volatile("cp.async.wait_group %0;" :: "n"(N) : "memory");
}

__device__ __forceinline__ void ldsm4(uint32_t* r, uint32_t addr) {
    asm volatile("ldmatrix.sync.aligned.m8n8.x4.shared.b16 {%0,%1,%2,%3}, [%4];"
                 : "=r"(r[0]), "=r"(r[1]), "=r"(r[2]), "=r"(r[3]) : "r"(addr));
}

__device__ __forceinline__ void mma16816(float* d, const uint32_t* a,
                                         uint32_t b0, uint32_t b1) {
    asm volatile(
        "mma.sync.aligned.m16n8k16.row.col.f32.bf16.bf16.f32 "
        "{%0,%1,%2,%3}, {%4,%5,%6,%7}, {%8,%9}, {%0,%1,%2,%3};\n"
        : "+f"(d[0]), "+f"(d[1]), "+f"(d[2]), "+f"(d[3])
        : "r"(a[0]), "r"(a[1]), "r"(a[2]), "r"(a[3]), "r"(b0), "r"(b1));
}

// Order-preserving float<->uint encoding for atomicMax on float
__device__ __forceinline__ unsigned int fenc(float f) {
    unsigned int u = __float_as_uint(f);
    return (u & 0x80000000u) ? ~u : (u | 0x80000000u);
}
__device__ __forceinline__ float fdec(unsigned int u) {
    u = (u & 0x80000000u) ? (u & 0x7FFFFFFFu) : ~u;
    return __uint_as_float(u);
}

// ---------------------------------------------------------------------------
__global__ void zero_kernel() {
    int i = blockIdx.x * blockDim.x + threadIdx.x;
    if (i < NROWS) {
        d_gsum[i] = 0.0f;
        d_gmax[i] = 0u;
        d_gd[i]   = 0.0f;
    }
    if (i == 0) { d_loss = 0.0f; d_correct = 0; }
}

// ---------------------------------------------------------------------------
// Normalize rows and split into bf16 (hi, lo): x = hi + lo (+ O(2^-18)).
__global__ void norm_kernel(const float* __restrict__ a,
                            const float* __restrict__ b) {
    int r = blockIdx.x;
    const float* src = (r < BATCH) ? a + (size_t)r * DIM
                                   : b + (size_t)(r - BATCH) * DIM;
    int t = threadIdx.x;   // 128 threads, 4 floats each
    float4 v = reinterpret_cast<const float4*>(src)[t];
    float ss = v.x * v.x + v.y * v.y + v.z * v.z + v.w * v.w;
    #pragma unroll
    for (int o = 16; o > 0; o >>= 1) ss += __shfl_xor_sync(0xffffffffu, ss, o);
    __shared__ float ws[4];
    if ((t & 31) == 0) ws[t >> 5] = ss;
    __syncthreads();
    float tot = ws[0] + ws[1] + ws[2] + ws[3];
    float scale = 1.0f / fmaxf(sqrtf(tot), 1e-12f);
    v.x *= scale; v.y *= scale; v.z *= scale; v.w *= scale;

    __nv_bfloat16 hx = __float2bfloat16(v.x);
    __nv_bfloat16 hy = __float2bfloat16(v.y);
    __nv_bfloat16 hz = __float2bfloat16(v.z);
    __nv_bfloat16 hw = __float2bfloat16(v.w);
    float lx = v.x - __bfloat162float(hx);
    float ly = v.y - __bfloat162float(hy);
    float lz = v.z - __bfloat162float(hz);
    float lw = v.w - __bfloat162float(hw);

    __nv_bfloat162* dh = reinterpret_cast<__nv_bfloat162*>(d_Xhi + (size_t)r * DIM);
    __nv_bfloat162* dl = reinterpret_cast<__nv_bfloat162*>(d_Xlo + (size_t)r * DIM);
    dh[2 * t]     = __nv_bfloat162(hx, hy);
    dh[2 * t + 1] = __nv_bfloat162(hz, hw);
    dl[2 * t]     = __floats2bfloat162_rn(lx, ly);
    dl[2 * t + 1] = __floats2bfloat162_rn(lz, lw);
}

// ---------------------------------------------------------------------------
// Gram kernel over the UPPER TRIANGLE of the 64x64 tile grid.
// Off-diagonal tile (bi < bj): row-scan feeds rows i0.., per-COLUMN reduction
// feeds rows j0.. (G symmetric). Diagonal tile: row-scan only, self excluded.
// Partner tiles (bj == bi^32): local diagonal yields d_gd for both rows.
__global__ __launch_bounds__(256, 2) void gram_kernel() {
    extern __shared__ __align__(1024) unsigned char smem[];
    uint32_t sbase = smem_to_u32(smem);

    const int tid  = threadIdx.x;
    const int lane = tid & 31;
    const int wid  = tid >> 5;
    const int wy   = wid & 3;    // M warp (4)
    const int wx   = wid >> 2;   // N warp (2)

    // Linear block id -> (bi, bj) with bi <= bj
    int t = blockIdx.x;
    int bi = (int)((129.0f - sqrtf(16641.0f - 8.0f * (float)t)) * 0.5f);
    if (bi < 0) bi = 0;
    if (bi > NTILE - 1) bi = NTILE - 1;
    while (bi > 0 && bi * NTILE - bi * (bi - 1) / 2 > t) bi--;
    while ((bi + 1) * NTILE - (bi + 1) * bi / 2 <= t) bi++;
    int bj = bi + (t - (bi * NTILE - bi * (bi - 1) / 2));

    const int i0 = bi * TM;
    const int j0 = bj * TN;
    const bool diag = (bi == bj);
    const bool part = (bj == (bi ^ (BATCH / TN)));   // bi<32, bj=bi+32

    float c[2][8][4];
    #pragma unroll
    for (int mt = 0; mt < 2; mt++)
        #pragma unroll
        for (int nt = 0; nt < 8; nt++)
            #pragma unroll
            for (int q = 0; q < 4; q++) c[mt][nt][q] = 0.0f;

    // cp.async loader: one stage = 2048 16B chunks, 8 per thread.
    auto load_stage = [&](int st, int k0) {
        #pragma unroll
        for (int it = 0; it < 8; it++) {
            int idx = tid + it * 256;
            int h = idx & 1;
            int r = (idx >> 1) & 127;
            int s = (idx >> 8) & 1;
            int m = idx >> 9;                     // 0=Ahi 1=Bhi 2=Alo 3=Blo
            int rowbase = (m & 1) ? j0 : i0;
            const __nv_bfloat16* g =
                ((m < 2) ? d_Xhi : d_Xlo) +
                (size_t)(rowbase + r) * DIM + k0 + s * 16 + h * 8;
            uint32_t dst = sbase + st * STAGEB +
                           ((m & 1) ? OFF_BHI : 0) + ((m >> 1) ? OFF_ALO : 0) +
                           s * SLICEB + r * ROWB + h * 16;
            cp_async16(dst, g);
        }
        cp_commit();
    };

    const uint32_t laneoff =
        (uint32_t)(((lane & 7) + ((lane >> 3) & 1) * 8) * ROWB + (lane >> 4) * 16);

    load_stage(0, 0);
    int stage = 0;

    for (int ch = 0; ch < NCHUNKS; ch++) {
        if (ch + 1 < NCHUNKS) load_stage(stage ^ 1, (ch + 1) * KC);
        if (ch + 1 < NCHUNKS) cp_wait<1>(); else cp_wait<0>();
        __syncthreads();

        uint32_t sb = sbase + stage * STAGEB;
        #pragma unroll
        for (int s = 0; s < 2; s++) {
            uint32_t slice = sb + s * SLICEB;
            uint32_t ahi[2][4], alo[2][4], bb[4][4];
            #pragma unroll
            for (int mt = 0; mt < 2; mt++) {
                uint32_t arow = (uint32_t)((wy * 32 + mt * 16) * ROWB) + laneoff;
                ldsm4(ahi[mt], slice + OFF_AHI + arow);
                ldsm4(alo[mt], slice + OFF_ALO + arow);
            }
            #pragma unroll
            for (int bt = 0; bt < 4; bt++) {
                uint32_t brow = (uint32_t)((wx * 64 + bt * 16) * ROWB) + laneoff;
                ldsm4(bb[bt], slice + OFF_BHI + brow);
            }
            #pragma unroll
            for (int mt = 0; mt < 2; mt++)
                #pragma unroll
                for (int bt = 0; bt < 4; bt++) {
                    mma16816(c[mt][bt * 2 + 0], ahi[mt], bb[bt][0], bb[bt][2]);
                    mma16816(c[mt][bt * 2 + 1], ahi[mt], bb[bt][1], bb[bt][3]);
                    mma16816(c[mt][bt * 2 + 0], alo[mt], bb[bt][0], bb[bt][2]);
                    mma16816(c[mt][bt * 2 + 1], alo[mt], bb[bt][1], bb[bt][3]);
                }
            #pragma unroll
            for (int bt = 0; bt < 4; bt++) {
                uint32_t brow = (uint32_t)((wx * 64 + bt * 16) * ROWB) + laneoff;
                ldsm4(bb[bt], slice + OFF_BLO + brow);
            }
            #pragma unroll
            for (int mt = 0; mt < 2; mt++)
                #pragma unroll
                for (int bt = 0; bt < 4; bt++) {
                    mma16816(c[mt][bt * 2 + 0], ahi[mt], bb[bt][0], bb[bt][2]);
                    mma16816(c[mt][bt * 2 + 1], ahi[mt], bb[bt][1], bb[bt][3]);
                }
        }
        __syncthreads();
        stage ^= 1;
    }

    // ---------------- Epilogue ----------------
    // Fragment mapping: row gr = i0 + wy*32 + mt*16 + (lane>>2) + 8*(q>>1)
    //                   col gc = j0 + wx*64 + nt*8 + 2*(lane&3) + (q&1)
    float rs[2][2], rm[2][2];
    #pragma unroll
    for (int mt = 0; mt < 2; mt++)
        #pragma unroll
        for (int h = 0; h < 2; h++) { rs[mt][h] = 0.0f; rm[mt][h] = -2.0f; }

    const int lrow0 = wy * 32 + (lane >> 2);       // + mt*16 + 8*(q>>1)
    const int lcol0 = wx * 64 + 2 * (lane & 3);    // + nt*8 + (q&1)

    #pragma unroll
    for (int nt = 0; nt < 8; nt++) {
        float cs0 = 0.0f, cs1 = 0.0f, cm0 = -2.0f, cm1 = -2.0f;
        #pragma unroll
        for (int mt = 0; mt < 2; mt++) {
            #pragma unroll
            for (int q = 0; q < 4; q++) {
                float v = c[mt][nt][q];
                int lr = lrow0 + mt * 16 + 8 * (q >> 1);
                int lc = lcol0 + nt * 8 + (q & 1);
                bool skip = diag && (lc == lr);
                float e = skip ? 0.0f : __expf(fmaf(TAU_INV, v, -TAU_INV));
                rs[mt][q >> 1] += e;
                if (!skip) rm[mt][q >> 1] = fmaxf(rm[mt][q >> 1], v);
                if (q & 1) { cs1 += e; cm1 = fmaxf(cm1, v); }
                else       { cs0 += e; cm0 = fmaxf(cm0, v); }
                if (part && lc == lr) {            // partner pair (one writer each)
                    d_gd[i0 + lr] = v;
                    d_gd[j0 + lc] = v;
                }
            }
        }
        if (!diag) {
            // Column reduction across rows held by other lanes (lane>>2 bits)
            #pragma unroll
            for (int o = 4; o <= 16; o <<= 1) {
                cs0 += __shfl_xor_sync(0xffffffffu, cs0, o);
                cs1 += __shfl_xor_sync(0xffffffffu, cs1, o);
                cm0 = fmaxf(cm0, __shfl_xor_sync(0xffffffffu, cm0, o));
                cm1 = fmaxf(cm1, __shfl_xor_sync(0xffffffffu, cm1, o));
            }
            if ((lane >> 2) == 0) {
                int gc0 = j0 + lcol0 + nt * 8;
                atomicAdd(&d_gsum[gc0],     cs0);
                atomicAdd(&d_gsum[gc0 + 1], cs1);
                if (gc0 < BATCH) {
                    atomicMax(&d_gmax[gc0],     fenc(cm0));
                    atomicMax(&d_gmax[gc0 + 1], fenc(cm1));
                }
            }
        }
    }

    // Row reduction across columns held by other lanes (lane&3 bits)
    #pragma unroll
    for (int mt = 0; mt < 2; mt++) {
        #pragma unroll
        for (int o = 1; o < 4; o <<= 1) {
            rs[mt][0] += __shfl_xor_sync(0xffffffffu, rs[mt][0], o);
            rs[mt][1] += __shfl_xor_sync(0xffffffffu, rs[mt][1], o);
            rm[mt][0] = fmaxf(rm[mt][0], __shfl_xor_sync(0xffffffffu, rm[mt][0], o));
            rm[mt][1] = fmaxf(rm[mt][1], __shfl_xor_sync(0xffffffffu, rm[mt][1], o));
        }
        if ((lane & 3) == 0) {
            int r0 = i0 + lrow0 + mt * 16;
            atomicAdd(&d_gsum[r0],     rs[mt][0]);
            atomicAdd(&d_gsum[r0 + 8], rs[mt][1]);
            if (r0 < BATCH) {
                atomicMax(&d_gmax[r0],     fenc(rm[mt][0]));
                atomicMax(&d_gmax[r0 + 8], fenc(rm[mt][1]));
            }
        }
    }
}

// ---------------------------------------------------------------------------
__global__ void finalize_kernel() {
    int r = blockIdx.x * blockDim.x + threadIdx.x;
    float lossv = 0.0f;
    int corr = 0;
    if (r < NROWS) {
        float s = d_gsum[r];
        float d = d_gd[r];
        // lse = 10 + log(sum exp(10c - 10));  label logit = 10*d
        lossv = (TAU_INV + __logf(s)) - TAU_INV * d;
        if (r < BATCH) {
            float m = fdec(d_gmax[r]);
            corr = (d >= m) ? 1 : 0;   // partner included in the max scan
        }
    }
    #pragma unroll
    for (int o = 16; o > 0; o >>= 1) {
        lossv += __shfl_xor_sync(0xffffffffu, lossv, o);
        corr  += __shfl_xor_sync(0xffffffffu, corr, o);
    }
    __shared__ float sl[8];
    __shared__ int   sc[8];
    int w = threadIdx.x >> 5, lane = threadIdx.x & 31;
    if (lane == 0) { sl[w] = lossv; sc[w] = corr; }
    __syncthreads();
    if (threadIdx.x == 0) {
        float L = 0.0f; int C = 0;
        #pragma unroll
        for (int i = 0; i < 8; i++) { L += sl[i]; C += sc[i]; }
        atomicAdd(&d_loss, L);
        atomicAdd(&d_correct, C);
    }
}

// ---------------------------------------------------------------------------
__global__ void writeout_kernel(float* out, int out_size) {
    if (threadIdx.x == 0) {
        out[0] = d_loss / (float)NROWS;
        if (out_size > 1)
            out[1] = 100.0f * (float)d_correct / (float)BATCH;
    }
}

// ---------------------------------------------------------------------------
extern "C" void kernel_launch(void* const* d_in, const int* in_sizes, int n_in,
                              void* d_out, int out_size) {
    const float* a = (const float*)d_in[0];
    const float* b = (const float*)d_in[1];
    float* out = (float*)d_out;

    cudaFuncSetAttribute(gram_kernel,
                         cudaFuncAttributeMaxDynamicSharedMemorySize, SMEM_TOTAL);

    zero_kernel<<<(NROWS + 255) / 256, 256>>>();
    norm_kernel<<<NROWS, 128>>>(a, b);
    gram_kernel<<<NBLOCKS, 256, SMEM_TOTAL>>>();
    finalize_kernel<<<NROWS / 256, 256>>>();
    writeout_kernel<<<1, 32>>>(out, out_size);
}

// round 7
// speedup vs baseline: 10.4685x; 2.2378x over previous
#include <cuda_runtime.h>
#include <cuda_fp16.h>
#include <math.h>
#include <stdint.h>

#define BATCH   4096
#define NROWS   8192
#define DIM     512
#define TAU_INV 10.0f

// Gram tiling
#define TM 128
#define TN 128
#define KC 32                 // k-chunk (2 k16 slices)
#define NCHUNKS (DIM / KC)    // 16
#define NTILE   (NROWS / TN)  // 64
#define NBLOCKS (NTILE * (NTILE + 1) / 2)   // 2080 upper-triangle tiles

// SMEM layout: padded rows (16 fp16 data + 8 fp16 pad = 48B) for conflict-free ldmatrix
#define ROWB   48
#define SLICEB (128 * ROWB)           // 6144
#define MATB   (2 * SLICEB)           // 12288 (2 k16 slices)
#define OFF_A  0
#define OFF_B  MATB
#define STAGEB (2 * MATB)             // 24576
#define SMEM_TOTAL (2 * STAGEB)       // 49152

// ---------------------------------------------------------------------------
// Scratch (device globals: no runtime allocation)
__device__ __half        d_Xh[(size_t)NROWS * DIM];   // 8 MB (L2-resident)
__device__ float         d_gsum[NROWS];
__device__ unsigned int  d_gmax[NROWS];
__device__ float         d_gd[NROWS];
__device__ float         d_loss;
__device__ int           d_correct;

// ---------------------------------------------------------------------------
__device__ __forceinline__ uint32_t smem_to_u32(const void* p) {
    uint32_t a;
    asm("{ .reg .u64 t; cvta.to.shared.u64 t, %1; cvt.u32.u64 %0, t; }"
        : "=r"(a) : "l"(p));
    return a;
}

__device__ __forceinline__ void cp_async16(uint32_t dst, const void* src) {
    asm volatile("cp.async.cg.shared.global [%0], [%1], 16;"
                 :: "r"(dst), "l"(src) : "memory");
}
__device__ __forceinline__ void cp_commit() {
    asm volatile("cp.async.commit_group;" ::: "memory");
}
template <int N>
__device__ __forceinline__ void cp_wait() {
    asm volatile("cp.async.wait_group %0;" :: "n"(N) : "memory");
}

__device__ __forceinline__ void ldsm4(uint32_t* r, uint32_t addr) {
    asm volatile("ldmatrix.sync.aligned.m8n8.x4.shared.b16 {%0,%1,%2,%3}, [%4];"
                 : "=r"(r[0]), "=r"(r[1]), "=r"(r[2]), "=r"(r[3]) : "r"(addr));
}

__device__ __forceinline__ void mma16816(float* d, const uint32_t* a,
                                         uint32_t b0, uint32_t b1) {
    asm volatile(
        "mma.sync.aligned.m16n8k16.row.col.f32.f16.f16.f32 "
        "{%0,%1,%2,%3}, {%4,%5,%6,%7}, {%8,%9}, {%0,%1,%2,%3};\n"
        : "+f"(d[0]), "+f"(d[1]), "+f"(d[2]), "+f"(d[3])
        : "r"(a[0]), "r"(a[1]), "r"(a[2]), "r"(a[3]), "r"(b0), "r"(b1));
}

// Order-preserving float<->uint encoding for atomicMax on float
__device__ __forceinline__ unsigned int fenc(float f) {
    unsigned int u = __float_as_uint(f);
    return (u & 0x80000000u) ? ~u : (u | 0x80000000u);
}
__device__ __forceinline__ float fdec(unsigned int u) {
    u = (u & 0x80000000u) ? (u & 0x7FFFFFFFu) : ~u;
    return __uint_as_float(u);
}

// ---------------------------------------------------------------------------
__global__ void zero_kernel() {
    int i = blockIdx.x * blockDim.x + threadIdx.x;
    if (i < NROWS) {
        d_gsum[i] = 0.0f;
        d_gmax[i] = 0u;
        d_gd[i]   = 0.0f;
    }
    if (i == 0) { d_loss = 0.0f; d_correct = 0; }
}

// ---------------------------------------------------------------------------
// Normalize rows, store fp16 (components <= 1, well inside fp16 range).
__global__ void norm_kernel(const float* __restrict__ a,
                            const float* __restrict__ b) {
    int r = blockIdx.x;
    const float* src = (r < BATCH) ? a + (size_t)r * DIM
                                   : b + (size_t)(r - BATCH) * DIM;
    int t = threadIdx.x;   // 128 threads, 4 floats each
    float4 v = reinterpret_cast<const float4*>(src)[t];
    float ss = v.x * v.x + v.y * v.y + v.z * v.z + v.w * v.w;
    #pragma unroll
    for (int o = 16; o > 0; o >>= 1) ss += __shfl_xor_sync(0xffffffffu, ss, o);
    __shared__ float ws[4];
    if ((t & 31) == 0) ws[t >> 5] = ss;
    __syncthreads();
    float tot = ws[0] + ws[1] + ws[2] + ws[3];
    float scale = 1.0f / fmaxf(sqrtf(tot), 1e-12f);

    __half2* dh = reinterpret_cast<__half2*>(d_Xh + (size_t)r * DIM);
    dh[2 * t]     = __floats2half2_rn(v.x * scale, v.y * scale);
    dh[2 * t + 1] = __floats2half2_rn(v.z * scale, v.w * scale);
}

// ---------------------------------------------------------------------------
// Gram kernel over the UPPER TRIANGLE of the 64x64 tile grid, single fp16
// MMA chain (fp32 accum). Off-diagonal tile (bi < bj): row-scan feeds rows
// i0.., per-COLUMN reduction feeds rows j0.. (G symmetric). Diagonal tile:
// row-scan only, self excluded. Partner tiles (bj == bi^32): local diagonal
// yields d_gd for both rows.
__global__ __launch_bounds__(256, 2) void gram_kernel() {
    extern __shared__ __align__(1024) unsigned char smem[];
    uint32_t sbase = smem_to_u32(smem);

    const int tid  = threadIdx.x;
    const int lane = tid & 31;
    const int wid  = tid >> 5;
    const int wy   = wid & 3;    // M warp (4)
    const int wx   = wid >> 2;   // N warp (2)

    // Linear block id -> (bi, bj) with bi <= bj
    int t = blockIdx.x;
    int bi = (int)((129.0f - sqrtf(16641.0f - 8.0f * (float)t)) * 0.5f);
    if (bi < 0) bi = 0;
    if (bi > NTILE - 1) bi = NTILE - 1;
    while (bi > 0 && bi * NTILE - bi * (bi - 1) / 2 > t) bi--;
    while ((bi + 1) * NTILE - (bi + 1) * bi / 2 <= t) bi++;
    int bj = bi + (t - (bi * NTILE - bi * (bi - 1) / 2));

    const int i0 = bi * TM;
    const int j0 = bj * TN;
    const bool diag = (bi == bj);
    const bool part = (bj == (bi ^ (BATCH / TN)));   // bi<32, bj=bi+32

    float c[2][8][4];
    #pragma unroll
    for (int mt = 0; mt < 2; mt++)
        #pragma unroll
        for (int nt = 0; nt < 8; nt++)
            #pragma unroll
            for (int q = 0; q < 4; q++) c[mt][nt][q] = 0.0f;

    // cp.async loader: one stage = 1024 16B chunks, 4 per thread.
    // idx bits: h=bit0, r=bits1..7, s=bit8, m=bit9 (0=A rows i0.., 1=B rows j0..)
    auto load_stage = [&](int st, int k0) {
        #pragma unroll
        for (int it = 0; it < 4; it++) {
            int idx = tid + it * 256;
            int h = idx & 1;
            int r = (idx >> 1) & 127;
            int s = (idx >> 8) & 1;
            int m = idx >> 9;
            int rowbase = m ? j0 : i0;
            const __half* g =
                d_Xh + (size_t)(rowbase + r) * DIM + k0 + s * 16 + h * 8;
            uint32_t dst = sbase + st * STAGEB + (m ? OFF_B : OFF_A) +
                           s * SLICEB + r * ROWB + h * 16;
            cp_async16(dst, g);
        }
        cp_commit();
    };

    const uint32_t laneoff =
        (uint32_t)(((lane & 7) + ((lane >> 3) & 1) * 8) * ROWB + (lane >> 4) * 16);

    load_stage(0, 0);
    int stage = 0;

    for (int ch = 0; ch < NCHUNKS; ch++) {
        if (ch + 1 < NCHUNKS) load_stage(stage ^ 1, (ch + 1) * KC);
        if (ch + 1 < NCHUNKS) cp_wait<1>(); else cp_wait<0>();
        __syncthreads();

        uint32_t sb = sbase + stage * STAGEB;
        #pragma unroll
        for (int s = 0; s < 2; s++) {
            uint32_t slice = sb + s * SLICEB;
            uint32_t aa[2][4], bb[4][4];
            #pragma unroll
            for (int mt = 0; mt < 2; mt++) {
                uint32_t arow = (uint32_t)((wy * 32 + mt * 16) * ROWB) + laneoff;
                ldsm4(aa[mt], slice + OFF_A + arow);
            }
            #pragma unroll
            for (int bt = 0; bt < 4; bt++) {
                uint32_t brow = (uint32_t)((wx * 64 + bt * 16) * ROWB) + laneoff;
                ldsm4(bb[bt], slice + OFF_B + brow);
            }
            #pragma unroll
            for (int mt = 0; mt < 2; mt++)
                #pragma unroll
                for (int bt = 0; bt < 4; bt++) {
                    mma16816(c[mt][bt * 2 + 0], aa[mt], bb[bt][0], bb[bt][2]);
                    mma16816(c[mt][bt * 2 + 1], aa[mt], bb[bt][1], bb[bt][3]);
                }
        }
        __syncthreads();
        stage ^= 1;
    }

    // ---------------- Epilogue ----------------
    // Fragment mapping: row gr = i0 + wy*32 + mt*16 + (lane>>2) + 8*(q>>1)
    //                   col gc = j0 + wx*64 + nt*8 + 2*(lane&3) + (q&1)
    float rs[2][2], rm[2][2];
    #pragma unroll
    for (int mt = 0; mt < 2; mt++)
        #pragma unroll
        for (int h = 0; h < 2; h++) { rs[mt][h] = 0.0f; rm[mt][h] = -2.0f; }

    const int lrow0 = wy * 32 + (lane >> 2);       // + mt*16 + 8*(q>>1)
    const int lcol0 = wx * 64 + 2 * (lane & 3);    // + nt*8 + (q&1)

    #pragma unroll
    for (int nt = 0; nt < 8; nt++) {
        float cs0 = 0.0f, cs1 = 0.0f, cm0 = -2.0f, cm1 = -2.0f;
        #pragma unroll
        for (int mt = 0; mt < 2; mt++) {
            #pragma unroll
            for (int q = 0; q < 4; q++) {
                float v = c[mt][nt][q];
                int lr = lrow0 + mt * 16 + 8 * (q >> 1);
                int lc = lcol0 + nt * 8 + (q & 1);
                bool skip = diag && (lc == lr);
                float e = skip ? 0.0f : __expf(fmaf(TAU_INV, v, -TAU_INV));
                rs[mt][q >> 1] += e;
                if (!skip) rm[mt][q >> 1] = fmaxf(rm[mt][q >> 1], v);
                if (q & 1) { cs1 += e; cm1 = fmaxf(cm1, v); }
                else       { cs0 += e; cm0 = fmaxf(cm0, v); }
                if (part && lc == lr) {            // partner pair (one writer each)
                    d_gd[i0 + lr] = v;
                    d_gd[j0 + lc] = v;
                }
            }
        }
        if (!diag) {
            // Column reduction across rows held by other lanes (lane>>2 bits)
            #pragma unroll
            for (int o = 4; o <= 16; o <<= 1) {
                cs0 += __shfl_xor_sync(0xffffffffu, cs0, o);
                cs1 += __shfl_xor_sync(0xffffffffu, cs1, o);
                cm0 = fmaxf(cm0, __shfl_xor_sync(0xffffffffu, cm0, o));
                cm1 = fmaxf(cm1, __shfl_xor_sync(0xffffffffu, cm1, o));
            }
            if ((lane >> 2) == 0) {
                int gc0 = j0 + lcol0 + nt * 8;
                atomicAdd(&d_gsum[gc0],     cs0);
                atomicAdd(&d_gsum[gc0 + 1], cs1);
                if (gc0 < BATCH) {
                    atomicMax(&d_gmax[gc0],     fenc(cm0));
                    atomicMax(&d_gmax[gc0 + 1], fenc(cm1));
                }
            }
        }
    }

    // Row reduction across columns held by other lanes (lane&3 bits)
    #pragma unroll
    for (int mt = 0; mt < 2; mt++) {
        #pragma unroll
        for (int o = 1; o < 4; o <<= 1) {
            rs[mt][0] += __shfl_xor_sync(0xffffffffu, rs[mt][0], o);
            rs[mt][1] += __shfl_xor_sync(0xffffffffu, rs[mt][1], o);
            rm[mt][0] = fmaxf(rm[mt][0], __shfl_xor_sync(0xffffffffu, rm[mt][0], o));
            rm[mt][1] = fmaxf(rm[mt][1], __shfl_xor_sync(0xffffffffu, rm[mt][1], o));
        }
        if ((lane & 3) == 0) {
            int r0 = i0 + lrow0 + mt * 16;
            atomicAdd(&d_gsum[r0],     rs[mt][0]);
            atomicAdd(&d_gsum[r0 + 8], rs[mt][1]);
            if (r0 < BATCH) {
                atomicMax(&d_gmax[r0],     fenc(rm[mt][0]));
                atomicMax(&d_gmax[r0 + 8], fenc(rm[mt][1]));
            }
        }
    }
}

// ---------------------------------------------------------------------------
__global__ void finalize_kernel() {
    int r = blockIdx.x * blockDim.x + threadIdx.x;
    float lossv = 0.0f;
    int corr = 0;
    if (r < NROWS) {
        float s = d_gsum[r];
        float d = d_gd[r];
        // lse = 10 + log(sum exp(10c - 10));  label logit = 10*d
        lossv = (TAU_INV + __logf(s)) - TAU_INV * d;
        if (r < BATCH) {
            float m = fdec(d_gmax[r]);
            corr = (d >= m) ? 1 : 0;   // partner included in the max scan
        }
    }
    #pragma unroll
    for (int o = 16; o > 0; o >>= 1) {
        lossv += __shfl_xor_sync(0xffffffffu, lossv, o);
        corr  += __shfl_xor_sync(0xffffffffu, corr, o);
    }
    __shared__ float sl[8];
    __shared__ int   sc[8];
    int w = threadIdx.x >> 5, lane = threadIdx.x & 31;
    if (lane == 0) { sl[w] = lossv; sc[w] = corr; }
    __syncthreads();
    if (threadIdx.x == 0) {
        float L = 0.0f; int C = 0;
        #pragma unroll
        for (int i = 0; i < 8; i++) { L += sl[i]; C += sc[i]; }
        atomicAdd(&d_loss, L);
        atomicAdd(&d_correct, C);
    }
}

// ---------------------------------------------------------------------------
__global__ void writeout_kernel(float* out, int out_size) {
    if (threadIdx.x == 0) {
        out[0] = d_loss / (float)NROWS;
        if (out_size > 1)
            out[1] = 100.0f * (float)d_correct / (float)BATCH;
    }
}

// ---------------------------------------------------------------------------
extern "C" void kernel_launch(void* const* d_in, const int* in_sizes, int n_in,
                              void* d_out, int out_size) {
    const float* a = (const float*)d_in[0];
    const float* b = (const float*)d_in[1];
    float* out = (float*)d_out;

    cudaFuncSetAttribute(gram_kernel,
                         cudaFuncAttributeMaxDynamicSharedMemorySize, SMEM_TOTAL);

    zero_kernel<<<(NROWS + 255) / 256, 256>>>();
    norm_kernel<<<NROWS, 128>>>(a, b);
    gram_kernel<<<NBLOCKS, 256, SMEM_TOTAL>>>();
    finalize_kernel<<<NROWS / 256, 256>>>();
    writeout_kernel<<<1, 32>>>(out, out_size);
}

// round 8
// speedup vs baseline: 12.2059x; 1.1660x over previous
#include <cuda_runtime.h>
#include <cuda_fp16.h>
#include <math.h>
#include <stdint.h>

#define BATCH   4096
#define NROWS   8192
#define DIM     512
#define TAU_INV 10.0f

// Gram tiling
#define TM 128
#define TN 128
#define KC 32                 // k-chunk (2 k16 slices)
#define NCHUNKS (DIM / KC)    // 16
#define NTILE   (NROWS / TN)  // 64
#define NBLOCKS (NTILE * (NTILE + 1) / 2)   // 2080 upper-triangle tiles
#define NSTAGES 3

// SMEM layout: padded rows (16 fp16 data + 8 fp16 pad = 48B) for conflict-free ldmatrix
#define ROWB   48
#define SLICEB (128 * ROWB)           // 6144
#define MATB   (2 * SLICEB)           // 12288 (2 k16 slices)
#define OFF_A  0
#define OFF_B  MATB
#define STAGEB (2 * MATB)             // 24576
#define SMEM_TOTAL (NSTAGES * STAGEB) // 73728

// ---------------------------------------------------------------------------
// Scratch (device globals: no runtime allocation)
__device__ __half        d_Xh[(size_t)NROWS * DIM];   // 8 MB (L2-resident)
__device__ float         d_gsum[NROWS];
__device__ unsigned int  d_gmax[NROWS];
__device__ float         d_gd[NROWS];

// ---------------------------------------------------------------------------
__device__ __forceinline__ uint32_t smem_to_u32(const void* p) {
    uint32_t a;
    asm("{ .reg .u64 t; cvta.to.shared.u64 t, %1; cvt.u32.u64 %0, t; }"
        : "=r"(a) : "l"(p));
    return a;
}

__device__ __forceinline__ void cp_async16(uint32_t dst, const void* src) {
    asm volatile("cp.async.cg.shared.global [%0], [%1], 16;"
                 :: "r"(dst), "l"(src) : "memory");
}
__device__ __forceinline__ void cp_commit() {
    asm volatile("cp.async.commit_group;" ::: "memory");
}
template <int N>
__device__ __forceinline__ void cp_wait() {
    asm volatile("cp.async.wait_group %0;" :: "n"(N) : "memory");
}

__device__ __forceinline__ void ldsm4(uint32_t* r, uint32_t addr) {
    asm volatile("ldmatrix.sync.aligned.m8n8.x4.shared.b16 {%0,%1,%2,%3}, [%4];"
                 : "=r"(r[0]), "=r"(r[1]), "=r"(r[2]), "=r"(r[3]) : "r"(addr));
}

__device__ __forceinline__ void mma16816(float* d, const uint32_t* a,
                                         uint32_t b0, uint32_t b1) {
    asm volatile(
        "mma.sync.aligned.m16n8k16.row.col.f32.f16.f16.f32 "
        "{%0,%1,%2,%3}, {%4,%5,%6,%7}, {%8,%9}, {%0,%1,%2,%3};\n"
        : "+f"(d[0]), "+f"(d[1]), "+f"(d[2]), "+f"(d[3])
        : "r"(a[0]), "r"(a[1]), "r"(a[2]), "r"(a[3]), "r"(b0), "r"(b1));
}

// Order-preserving float<->uint encoding for atomicMax on float
__device__ __forceinline__ unsigned int fenc(float f) {
    unsigned int u = __float_as_uint(f);
    return (u & 0x80000000u) ? ~u : (u | 0x80000000u);
}
__device__ __forceinline__ float fdec(unsigned int u) {
    u = (u & 0x80000000u) ? (u & 0x7FFFFFFFu) : ~u;
    return __uint_as_float(u);
}

// ---------------------------------------------------------------------------
// Normalize rows, store fp16; also zero this row's accumulators (fused zero).
__global__ void norm_kernel(const float* __restrict__ a,
                            const float* __restrict__ b) {
    int r = blockIdx.x;
    const float* src = (r < BATCH) ? a + (size_t)r * DIM
                                   : b + (size_t)(r - BATCH) * DIM;
    int t = threadIdx.x;   // 128 threads, 4 floats each
    if (t == 0) {
        d_gsum[r] = 0.0f;
        d_gmax[r] = 0u;
        d_gd[r]   = 0.0f;
    }
    float4 v = reinterpret_cast<const float4*>(src)[t];
    float ss = v.x * v.x + v.y * v.y + v.z * v.z + v.w * v.w;
    #pragma unroll
    for (int o = 16; o > 0; o >>= 1) ss += __shfl_xor_sync(0xffffffffu, ss, o);
    __shared__ float ws[4];
    if ((t & 31) == 0) ws[t >> 5] = ss;
    __syncthreads();
    float tot = ws[0] + ws[1] + ws[2] + ws[3];
    float scale = 1.0f / fmaxf(sqrtf(tot), 1e-12f);

    __half2* dh = reinterpret_cast<__half2*>(d_Xh + (size_t)r * DIM);
    dh[2 * t]     = __floats2half2_rn(v.x * scale, v.y * scale);
    dh[2 * t + 1] = __floats2half2_rn(v.z * scale, v.w * scale);
}

// ---------------------------------------------------------------------------
// Gram kernel over the UPPER TRIANGLE of the 64x64 tile grid, single fp16
// MMA chain (fp32 accum), 3-stage cp.async pipeline, one barrier per chunk.
// Off-diagonal tile (bi < bj): row-scan feeds rows i0.., per-COLUMN reduction
// feeds rows j0.. (G symmetric). Diagonal tile: row-scan only, self excluded.
// Partner tiles (bj == bi^32): local diagonal yields d_gd for both rows.
__global__ __launch_bounds__(256, 2) void gram_kernel() {
    extern __shared__ __align__(1024) unsigned char smem[];
    uint32_t sbase = smem_to_u32(smem);

    const int tid  = threadIdx.x;
    const int lane = tid & 31;
    const int wid  = tid >> 5;
    const int wy   = wid & 3;    // M warp (4)
    const int wx   = wid >> 2;   // N warp (2)

    // Linear block id -> (bi, bj) with bi <= bj
    int t = blockIdx.x;
    int bi = (int)((129.0f - sqrtf(16641.0f - 8.0f * (float)t)) * 0.5f);
    if (bi < 0) bi = 0;
    if (bi > NTILE - 1) bi = NTILE - 1;
    while (bi > 0 && bi * NTILE - bi * (bi - 1) / 2 > t) bi--;
    while ((bi + 1) * NTILE - (bi + 1) * bi / 2 <= t) bi++;
    int bj = bi + (t - (bi * NTILE - bi * (bi - 1) / 2));

    const int i0 = bi * TM;
    const int j0 = bj * TN;
    const bool diag = (bi == bj);
    const bool part = (bj == (bi ^ (BATCH / TN)));   // bi<32, bj=bi+32

    float c[2][8][4];
    #pragma unroll
    for (int mt = 0; mt < 2; mt++)
        #pragma unroll
        for (int nt = 0; nt < 8; nt++)
            #pragma unroll
            for (int q = 0; q < 4; q++) c[mt][nt][q] = 0.0f;

    // cp.async loader: one stage = 1024 16B chunks, 4 per thread.
    // idx bits: h=bit0, r=bits1..7, s=bit8, m=bit9 (0=A rows i0.., 1=B rows j0..)
    auto load_stage = [&](int st, int k0) {
        #pragma unroll
        for (int it = 0; it < 4; it++) {
            int idx = tid + it * 256;
            int h = idx & 1;
            int r = (idx >> 1) & 127;
            int s = (idx >> 8) & 1;
            int m = idx >> 9;
            int rowbase = m ? j0 : i0;
            const __half* g =
                d_Xh + (size_t)(rowbase + r) * DIM + k0 + s * 16 + h * 8;
            uint32_t dst = sbase + st * STAGEB + (m ? OFF_B : OFF_A) +
                           s * SLICEB + r * ROWB + h * 16;
            cp_async16(dst, g);
        }
        cp_commit();
    };

    const uint32_t laneoff =
        (uint32_t)(((lane & 7) + ((lane >> 3) & 1) * 8) * ROWB + (lane >> 4) * 16);

    // Prologue: two chunks in flight
    load_stage(0, 0);
    load_stage(1, KC);

    for (int ch = 0; ch < NCHUNKS; ch++) {
        // Ensure chunk ch's data has landed (FIFO: <=1 pending leaves ch+1 only)
        if (ch + 2 < NCHUNKS) cp_wait<1>(); else cp_wait<0>();
        __syncthreads();   // all warps done with stage (ch-1)%3; ch%3 visible

        if (ch + 2 < NCHUNKS) load_stage((ch + 2) % NSTAGES, (ch + 2) * KC);

        uint32_t sb = sbase + (ch % NSTAGES) * STAGEB;
        #pragma unroll
        for (int s = 0; s < 2; s++) {
            uint32_t slice = sb + s * SLICEB;
            uint32_t aa[2][4], bb[4][4];
            #pragma unroll
            for (int mt = 0; mt < 2; mt++) {
                uint32_t arow = (uint32_t)((wy * 32 + mt * 16) * ROWB) + laneoff;
                ldsm4(aa[mt], slice + OFF_A + arow);
            }
            #pragma unroll
            for (int bt = 0; bt < 4; bt++) {
                uint32_t brow = (uint32_t)((wx * 64 + bt * 16) * ROWB) + laneoff;
                ldsm4(bb[bt], slice + OFF_B + brow);
            }
            #pragma unroll
            for (int mt = 0; mt < 2; mt++)
                #pragma unroll
                for (int bt = 0; bt < 4; bt++) {
                    mma16816(c[mt][bt * 2 + 0], aa[mt], bb[bt][0], bb[bt][2]);
                    mma16816(c[mt][bt * 2 + 1], aa[mt], bb[bt][1], bb[bt][3]);
                }
        }
    }

    // ---------------- Epilogue ----------------
    // Fragment mapping: row gr = i0 + wy*32 + mt*16 + (lane>>2) + 8*(q>>1)
    //                   col gc = j0 + wx*64 + nt*8 + 2*(lane&3) + (q&1)
    float rs[2][2], rm[2][2];
    #pragma unroll
    for (int mt = 0; mt < 2; mt++)
        #pragma unroll
        for (int h = 0; h < 2; h++) { rs[mt][h] = 0.0f; rm[mt][h] = -2.0f; }

    const int lrow0 = wy * 32 + (lane >> 2);       // + mt*16 + 8*(q>>1)
    const int lcol0 = wx * 64 + 2 * (lane & 3);    // + nt*8 + (q&1)

    #pragma unroll
    for (int nt = 0; nt < 8; nt++) {
        float cs0 = 0.0f, cs1 = 0.0f, cm0 = -2.0f, cm1 = -2.0f;
        #pragma unroll
        for (int mt = 0; mt < 2; mt++) {
            #pragma unroll
            for (int q = 0; q < 4; q++) {
                float v = c[mt][nt][q];
                int lr = lrow0 + mt * 16 + 8 * (q >> 1);
                int lc = lcol0 + nt * 8 + (q & 1);
                bool skip = diag && (lc == lr);
                float e = skip ? 0.0f : __expf(fmaf(TAU_INV, v, -TAU_INV));
                rs[mt][q >> 1] += e;
                if (!skip) rm[mt][q >> 1] = fmaxf(rm[mt][q >> 1], v);
                if (q & 1) { cs1 += e; cm1 = fmaxf(cm1, v); }
                else       { cs0 += e; cm0 = fmaxf(cm0, v); }
                if (part && lc == lr) {            // partner pair (one writer each)
                    d_gd[i0 + lr] = v;
                    d_gd[j0 + lc] = v;
                }
            }
        }
        if (!diag) {
            // Column reduction across rows held by other lanes (lane>>2 bits)
            #pragma unroll
            for (int o = 4; o <= 16; o <<= 1) {
                cs0 += __shfl_xor_sync(0xffffffffu, cs0, o);
                cs1 += __shfl_xor_sync(0xffffffffu, cs1, o);
                cm0 = fmaxf(cm0, __shfl_xor_sync(0xffffffffu, cm0, o));
                cm1 = fmaxf(cm1, __shfl_xor_sync(0xffffffffu, cm1, o));
            }
            if ((lane >> 2) == 0) {
                int gc0 = j0 + lcol0 + nt * 8;
                atomicAdd(&d_gsum[gc0],     cs0);
                atomicAdd(&d_gsum[gc0 + 1], cs1);
                if (gc0 < BATCH) {
                    atomicMax(&d_gmax[gc0],     fenc(cm0));
                    atomicMax(&d_gmax[gc0 + 1], fenc(cm1));
                }
            }
        }
    }

    // Row reduction across columns held by other lanes (lane&3 bits)
    #pragma unroll
    for (int mt = 0; mt < 2; mt++) {
        #pragma unroll
        for (int o = 1; o < 4; o <<= 1) {
            rs[mt][0] += __shfl_xor_sync(0xffffffffu, rs[mt][0], o);
            rs[mt][1] += __shfl_xor_sync(0xffffffffu, rs[mt][1], o);
            rm[mt][0] = fmaxf(rm[mt][0], __shfl_xor_sync(0xffffffffu, rm[mt][0], o));
            rm[mt][1] = fmaxf(rm[mt][1], __shfl_xor_sync(0xffffffffu, rm[mt][1], o));
        }
        if ((lane & 3) == 0) {
            int r0 = i0 + lrow0 + mt * 16;
            atomicAdd(&d_gsum[r0],     rs[mt][0]);
            atomicAdd(&d_gsum[r0 + 8], rs[mt][1]);
            if (r0 < BATCH) {
                atomicMax(&d_gmax[r0],     fenc(rm[mt][0]));
                atomicMax(&d_gmax[r0 + 8], fenc(rm[mt][1]));
            }
        }
    }
}

// ---------------------------------------------------------------------------
// Single-block finalize + writeout (no global atomics, deterministic order).
__global__ __launch_bounds__(1024) void finalize_kernel(float* out, int out_size) {
    int tid = threadIdx.x;
    float lossv = 0.0f;
    int corr = 0;
    for (int r = tid; r < NROWS; r += 1024) {
        float s = d_gsum[r];
        float d = d_gd[r];
        // lse = 10 + log(sum exp(10c - 10));  label logit = 10*d
        lossv += (TAU_INV + __logf(s)) - TAU_INV * d;
        if (r < BATCH) {
            float m = fdec(d_gmax[r]);
            corr += (d >= m) ? 1 : 0;   // partner included in the max scan
        }
    }
    #pragma unroll
    for (int o = 16; o > 0; o >>= 1) {
        lossv += __shfl_xor_sync(0xffffffffu, lossv, o);
        corr  += __shfl_xor_sync(0xffffffffu, corr, o);
    }
    __shared__ float sl[32];
    __shared__ int   sc[32];
    int w = tid >> 5, lane = tid & 31;
    if (lane == 0) { sl[w] = lossv; sc[w] = corr; }
    __syncthreads();
    if (tid == 0) {
        float L = 0.0f; int C = 0;
        #pragma unroll
        for (int i = 0; i < 32; i++) { L += sl[i]; C += sc[i]; }
        out[0] = L / (float)NROWS;
        if (out_size > 1)
            out[1] = 100.0f * (float)C / (float)BATCH;
    }
}

// ---------------------------------------------------------------------------
extern "C" void kernel_launch(void* const* d_in, const int* in_sizes, int n_in,
                              void* d_out, int out_size) {
    const float* a = (const float*)d_in[0];
    const float* b = (const float*)d_in[1];
    float* out = (float*)d_out;

    cudaFuncSetAttribute(gram_kernel,
                         cudaFuncAttributeMaxDynamicSharedMemorySize, SMEM_TOTAL);

    norm_kernel<<<NROWS, 128>>>(a, b);
    gram_kernel<<<NBLOCKS, 256, SMEM_TOTAL>>>();
    finalize_kernel<<<1, 1024>>>(out, out_size);
}

// round 9
// speedup vs baseline: 12.6770x; 1.0386x over previous
#include <cuda_runtime.h>
#include <cuda_fp16.h>
#include <math.h>
#include <stdint.h>

#define BATCH   4096
#define NROWS   8192
#define DIM     512
#define TAU_INV 10.0f

// Gram tiling
#define TM 128
#define TN 128
#define KC 32                 // k-chunk (2 k16 slices)
#define NCHUNKS (DIM / KC)    // 16
#define NTILE   (NROWS / TN)  // 64
#define NBLOCKS (NTILE * (NTILE + 1) / 2)   // 2080 upper-triangle tiles
#define NSTAGES 3

// SMEM layout: padded rows (16 fp16 data + 8 fp16 pad = 48B) for conflict-free ldmatrix
#define ROWB   48
#define SLICEB (128 * ROWB)           // 6144
#define MATB   (2 * SLICEB)           // 12288 (2 k16 slices)
#define OFF_A  0
#define OFF_B  MATB
#define STAGEB (2 * MATB)             // 24576
#define SMEM_TOTAL (NSTAGES * STAGEB) // 73728

// ---------------------------------------------------------------------------
// Scratch (device globals: no runtime allocation)
__device__ __half        d_Xh[(size_t)NROWS * DIM];   // 8 MB (L2-resident)
__device__ float         d_gsum[NROWS];
__device__ unsigned int  d_gmax[NROWS];
__device__ float         d_gd[NROWS];

// ---------------------------------------------------------------------------
__device__ __forceinline__ uint32_t smem_to_u32(const void* p) {
    uint32_t a;
    asm("{ .reg .u64 t; cvta.to.shared.u64 t, %1; cvt.u32.u64 %0, t; }"
        : "=r"(a) : "l"(p));
    return a;
}

__device__ __forceinline__ void cp_async16(uint32_t dst, const void* src) {
    asm volatile("cp.async.cg.shared.global [%0], [%1], 16;"
                 :: "r"(dst), "l"(src) : "memory");
}
__device__ __forceinline__ void cp_commit() {
    asm volatile("cp.async.commit_group;" ::: "memory");
}
template <int N>
__device__ __forceinline__ void cp_wait() {
    asm volatile("cp.async.wait_group %0;" :: "n"(N) : "memory");
}

__device__ __forceinline__ void ldsm4(uint32_t* r, uint32_t addr) {
    asm volatile("ldmatrix.sync.aligned.m8n8.x4.shared.b16 {%0,%1,%2,%3}, [%4];"
                 : "=r"(r[0]), "=r"(r[1]), "=r"(r[2]), "=r"(r[3]) : "r"(addr));
}

__device__ __forceinline__ void mma16816(float* d, const uint32_t* a,
                                         uint32_t b0, uint32_t b1) {
    asm volatile(
        "mma.sync.aligned.m16n8k16.row.col.f32.f16.f16.f32 "
        "{%0,%1,%2,%3}, {%4,%5,%6,%7}, {%8,%9}, {%0,%1,%2,%3};\n"
        : "+f"(d[0]), "+f"(d[1]), "+f"(d[2]), "+f"(d[3])
        : "r"(a[0]), "r"(a[1]), "r"(a[2]), "r"(a[3]), "r"(b0), "r"(b1));
}

// Order-preserving float<->uint encoding for atomicMax on float
__device__ __forceinline__ unsigned int fenc(float f) {
    unsigned int u = __float_as_uint(f);
    return (u & 0x80000000u) ? ~u : (u | 0x80000000u);
}
__device__ __forceinline__ float fdec(unsigned int u) {
    u = (u & 0x80000000u) ? (u & 0x7FFFFFFFu) : ~u;
    return __uint_as_float(u);
}

// ---------------------------------------------------------------------------
// Normalize rows -> fp16, warp-per-row (MLP=4, warp-local reduction only).
// Also zeroes the row's accumulators (fused zero).
__global__ __launch_bounds__(256) void norm_kernel(const float* __restrict__ a,
                                                   const float* __restrict__ b) {
    int lane = threadIdx.x & 31;
    int r = blockIdx.x * 8 + (threadIdx.x >> 5);
    const float* src = (r < BATCH) ? a + (size_t)r * DIM
                                   : b + (size_t)(r - BATCH) * DIM;

    if (lane == 0) {
        d_gsum[r] = 0.0f;
        d_gmax[r] = 0u;
        d_gd[r]   = 0.0f;
    }

    // 4 independent float4 loads per lane (coalesced, MLP=4)
    float4 v[4];
    #pragma unroll
    for (int i = 0; i < 4; i++)
        v[i] = reinterpret_cast<const float4*>(src)[lane + 32 * i];

    float ss = 0.0f;
    #pragma unroll
    for (int i = 0; i < 4; i++)
        ss += v[i].x * v[i].x + v[i].y * v[i].y + v[i].z * v[i].z + v[i].w * v[i].w;
    #pragma unroll
    for (int o = 16; o > 0; o >>= 1) ss += __shfl_xor_sync(0xffffffffu, ss, o);

    float scale = 1.0f / fmaxf(sqrtf(ss), 1e-12f);

    uint2* dh = reinterpret_cast<uint2*>(d_Xh + (size_t)r * DIM);
    #pragma unroll
    for (int i = 0; i < 4; i++) {
        __half2 h0 = __floats2half2_rn(v[i].x * scale, v[i].y * scale);
        __half2 h1 = __floats2half2_rn(v[i].z * scale, v[i].w * scale);
        uint2 pk;
        pk.x = *reinterpret_cast<uint32_t*>(&h0);
        pk.y = *reinterpret_cast<uint32_t*>(&h1);
        dh[lane + 32 * i] = pk;
    }
}

// ---------------------------------------------------------------------------
// Gram kernel over the UPPER TRIANGLE of the 64x64 tile grid, single fp16
// MMA chain (fp32 accum), 3-stage cp.async pipeline, one barrier per chunk.
// Off-diagonal tile (bi < bj): row-scan feeds rows i0.., per-COLUMN reduction
// feeds rows j0.. (G symmetric). Diagonal tile: row-scan only, self excluded.
// Partner tiles (bj == bi^32): local diagonal yields d_gd for both rows.
__global__ __launch_bounds__(256, 2) void gram_kernel() {
    extern __shared__ __align__(1024) unsigned char smem[];
    uint32_t sbase = smem_to_u32(smem);

    const int tid  = threadIdx.x;
    const int lane = tid & 31;
    const int wid  = tid >> 5;
    const int wy   = wid & 3;    // M warp (4)
    const int wx   = wid >> 2;   // N warp (2)

    // Linear block id -> (bi, bj) with bi <= bj
    int t = blockIdx.x;
    int bi = (int)((129.0f - sqrtf(16641.0f - 8.0f * (float)t)) * 0.5f);
    if (bi < 0) bi = 0;
    if (bi > NTILE - 1) bi = NTILE - 1;
    while (bi > 0 && bi * NTILE - bi * (bi - 1) / 2 > t) bi--;
    while ((bi + 1) * NTILE - (bi + 1) * bi / 2 <= t) bi++;
    int bj = bi + (t - (bi * NTILE - bi * (bi - 1) / 2));

    const int i0 = bi * TM;
    const int j0 = bj * TN;
    const bool diag = (bi == bj);
    const bool part = (bj == (bi ^ (BATCH / TN)));   // bi<32, bj=bi+32

    float c[2][8][4];
    #pragma unroll
    for (int mt = 0; mt < 2; mt++)
        #pragma unroll
        for (int nt = 0; nt < 8; nt++)
            #pragma unroll
            for (int q = 0; q < 4; q++) c[mt][nt][q] = 0.0f;

    // cp.async loader: one stage = 1024 16B chunks, 4 per thread.
    // idx bits: h=bit0, r=bits1..7, s=bit8, m=bit9 (0=A rows i0.., 1=B rows j0..)
    auto load_stage = [&](int st, int k0) {
        #pragma unroll
        for (int it = 0; it < 4; it++) {
            int idx = tid + it * 256;
            int h = idx & 1;
            int r = (idx >> 1) & 127;
            int s = (idx >> 8) & 1;
            int m = idx >> 9;
            int rowbase = m ? j0 : i0;
            const __half* g =
                d_Xh + (size_t)(rowbase + r) * DIM + k0 + s * 16 + h * 8;
            uint32_t dst = sbase + st * STAGEB + (m ? OFF_B : OFF_A) +
                           s * SLICEB + r * ROWB + h * 16;
            cp_async16(dst, g);
        }
        cp_commit();
    };

    const uint32_t laneoff =
        (uint32_t)(((lane & 7) + ((lane >> 3) & 1) * 8) * ROWB + (lane >> 4) * 16);

    // Prologue: two chunks in flight
    load_stage(0, 0);
    load_stage(1, KC);

    for (int ch = 0; ch < NCHUNKS; ch++) {
        // Ensure chunk ch's data has landed (FIFO: <=1 pending leaves ch+1 only)
        if (ch + 2 < NCHUNKS) cp_wait<1>(); else cp_wait<0>();
        __syncthreads();   // all warps done with stage (ch-1)%3; ch%3 visible

        if (ch + 2 < NCHUNKS) load_stage((ch + 2) % NSTAGES, (ch + 2) * KC);

        uint32_t sb = sbase + (ch % NSTAGES) * STAGEB;
        #pragma unroll
        for (int s = 0; s < 2; s++) {
            uint32_t slice = sb + s * SLICEB;
            uint32_t aa[2][4], bb[4][4];
            #pragma unroll
            for (int mt = 0; mt < 2; mt++) {
                uint32_t arow = (uint32_t)((wy * 32 + mt * 16) * ROWB) + laneoff;
                ldsm4(aa[mt], slice + OFF_A + arow);
            }
            #pragma unroll
            for (int bt = 0; bt < 4; bt++) {
                uint32_t brow = (uint32_t)((wx * 64 + bt * 16) * ROWB) + laneoff;
                ldsm4(bb[bt], slice + OFF_B + brow);
            }
            #pragma unroll
            for (int mt = 0; mt < 2; mt++)
                #pragma unroll
                for (int bt = 0; bt < 4; bt++) {
                    mma16816(c[mt][bt * 2 + 0], aa[mt], bb[bt][0], bb[bt][2]);
                    mma16816(c[mt][bt * 2 + 1], aa[mt], bb[bt][1], bb[bt][3]);
                }
        }
    }

    // ---------------- Epilogue ----------------
    // Fragment mapping: row gr = i0 + wy*32 + mt*16 + (lane>>2) + 8*(q>>1)
    //                   col gc = j0 + wx*64 + nt*8 + 2*(lane&3) + (q&1)
    float rs[2][2], rm[2][2];
    #pragma unroll
    for (int mt = 0; mt < 2; mt++)
        #pragma unroll
        for (int h = 0; h < 2; h++) { rs[mt][h] = 0.0f; rm[mt][h] = -2.0f; }

    const int lrow0 = wy * 32 + (lane >> 2);       // + mt*16 + 8*(q>>1)
    const int lcol0 = wx * 64 + 2 * (lane & 3);    // + nt*8 + (q&1)

    #pragma unroll
    for (int nt = 0; nt < 8; nt++) {
        float cs0 = 0.0f, cs1 = 0.0f, cm0 = -2.0f, cm1 = -2.0f;
        #pragma unroll
        for (int mt = 0; mt < 2; mt++) {
            #pragma unroll
            for (int q = 0; q < 4; q++) {
                float v = c[mt][nt][q];
                int lr = lrow0 + mt * 16 + 8 * (q >> 1);
                int lc = lcol0 + nt * 8 + (q & 1);
                bool skip = diag && (lc == lr);
                float e = skip ? 0.0f : __expf(fmaf(TAU_INV, v, -TAU_INV));
                rs[mt][q >> 1] += e;
                if (!skip) rm[mt][q >> 1] = fmaxf(rm[mt][q >> 1], v);
                if (q & 1) { cs1 += e; cm1 = fmaxf(cm1, v); }
                else       { cs0 += e; cm0 = fmaxf(cm0, v); }
                if (part && lc == lr) {            // partner pair (one writer each)
                    d_gd[i0 + lr] = v;
                    d_gd[j0 + lc] = v;
                }
            }
        }
        if (!diag) {
            // Column reduction across rows held by other lanes (lane>>2 bits)
            #pragma unroll
            for (int o = 4; o <= 16; o <<= 1) {
                cs0 += __shfl_xor_sync(0xffffffffu, cs0, o);
                cs1 += __shfl_xor_sync(0xffffffffu, cs1, o);
                cm0 = fmaxf(cm0, __shfl_xor_sync(0xffffffffu, cm0, o));
                cm1 = fmaxf(cm1, __shfl_xor_sync(0xffffffffu, cm1, o));
            }
            if ((lane >> 2) == 0) {
                int gc0 = j0 + lcol0 + nt * 8;
                atomicAdd(&d_gsum[gc0],     cs0);
                atomicAdd(&d_gsum[gc0 + 1], cs1);
                if (gc0 < BATCH) {
                    atomicMax(&d_gmax[gc0],     fenc(cm0));
                    atomicMax(&d_gmax[gc0 + 1], fenc(cm1));
                }
            }
        }
    }

    // Row reduction across columns held by other lanes (lane&3 bits)
    #pragma unroll
    for (int mt = 0; mt < 2; mt++) {
        #pragma unroll
        for (int o = 1; o < 4; o <<= 1) {
            rs[mt][0] += __shfl_xor_sync(0xffffffffu, rs[mt][0], o);
            rs[mt][1] += __shfl_xor_sync(0xffffffffu, rs[mt][1], o);
            rm[mt][0] = fmaxf(rm[mt][0], __shfl_xor_sync(0xffffffffu, rm[mt][0], o));
            rm[mt][1] = fmaxf(rm[mt][1], __shfl_xor_sync(0xffffffffu, rm[mt][1], o));
        }
        if ((lane & 3) == 0) {
            int r0 = i0 + lrow0 + mt * 16;
            atomicAdd(&d_gsum[r0],     rs[mt][0]);
            atomicAdd(&d_gsum[r0 + 8], rs[mt][1]);
            if (r0 < BATCH) {
                atomicMax(&d_gmax[r0],     fenc(rm[mt][0]));
                atomicMax(&d_gmax[r0 + 8], fenc(rm[mt][1]));
            }
        }
    }
}

// ---------------------------------------------------------------------------
// Single-block finalize + writeout. Prefetch all loads before dependent math.
__global__ __launch_bounds__(1024) void finalize_kernel(float* out, int out_size) {
    int tid = threadIdx.x;
    float sv[8], dv[8];
    unsigned int mv[4];
    #pragma unroll
    for (int i = 0; i < 8; i++) {
        int r = tid + i * 1024;
        sv[i] = d_gsum[r];
        dv[i] = d_gd[r];
    }
    #pragma unroll
    for (int i = 0; i < 4; i++)
        mv[i] = d_gmax[tid + i * 1024];

    float lossv = 0.0f;
    int corr = 0;
    #pragma unroll
    for (int i = 0; i < 8; i++)
        lossv += (TAU_INV + __logf(sv[i])) - TAU_INV * dv[i];
    #pragma unroll
    for (int i = 0; i < 4; i++)
        corr += (dv[i] >= fdec(mv[i])) ? 1 : 0;  // rows < BATCH only

    #pragma unroll
    for (int o = 16; o > 0; o >>= 1) {
        lossv += __shfl_xor_sync(0xffffffffu, lossv, o);
        corr  += __shfl_xor_sync(0xffffffffu, corr, o);
    }
    __shared__ float sl[32];
    __shared__ int   sc[32];
    int w = tid >> 5, lane = tid & 31;
    if (lane == 0) { sl[w] = lossv; sc[w] = corr; }
    __syncthreads();
    if (tid == 0) {
        float L = 0.0f; int C = 0;
        #pragma unroll
        for (int i = 0; i < 32; i++) { L += sl[i]; C += sc[i]; }
        out[0] = L / (float)NROWS;
        if (out_size > 1)
            out[1] = 100.0f * (float)C / (float)BATCH;
    }
}

// ---------------------------------------------------------------------------
extern "C" void kernel_launch(void* const* d_in, const int* in_sizes, int n_in,
                              void* d_out, int out_size) {
    const float* a = (const float*)d_in[0];
    const float* b = (const float*)d_in[1];
    float* out = (float*)d_out;

    cudaFuncSetAttribute(gram_kernel,
                         cudaFuncAttributeMaxDynamicSharedMemorySize, SMEM_TOTAL);

    norm_kernel<<<NROWS / 8, 256>>>(a, b);
    gram_kernel<<<NBLOCKS, 256, SMEM_TOTAL>>>();
    finalize_kernel<<<1, 1024>>>(out, out_size);
}